// round 1
// baseline (speedup 1.0000x reference)
#include <cuda_runtime.h>
#include <cuda_bf16.h>

#define N_NODES  100000
#define N_EDGES  1600000
#define NFEAT    602
#define HID      128
#define NCLS     41

// ---------------- device scratch (no allocations allowed) ----------------
__device__ int   g_deg_in[N_NODES];
__device__ int   g_deg_out[N_NODES];
__device__ float g_ns[N_NODES];          // deg_out^-1/2 (clipped)
__device__ float g_nd[N_NODES];          // deg_in^-1/2  (clipped)
__device__ int   g_incl[N_NODES];        // inclusive prefix sum of deg_in
__device__ int   g_blocksum[256];
__device__ int   g_cursor[N_NODES];
__device__ int   g_csr[N_EDGES];         // src ids grouped by dst
__device__ __align__(16) float g_h1 [(size_t)N_NODES * HID];
__device__ __align__(16) float g_h1b[(size_t)N_NODES * HID];
__device__ __align__(16) float g_h2 [(size_t)N_NODES * NCLS];

// ---------------- degree / norm / CSR build ----------------
__global__ void k_zero_deg() {
    int i = blockIdx.x * blockDim.x + threadIdx.x;
    if (i < N_NODES) { g_deg_in[i] = 0; g_deg_out[i] = 0; }
}

__global__ void k_count(const int* __restrict__ src, const int* __restrict__ dst) {
    int e = blockIdx.x * blockDim.x + threadIdx.x;
    if (e < N_EDGES) {
        atomicAdd(&g_deg_out[src[e]], 1);
        atomicAdd(&g_deg_in [dst[e]], 1);
    }
}

// block-local inclusive scan of deg_in (1024 per block)
__global__ void k_scan_block() {
    __shared__ int s[1024];
    int i = blockIdx.x * 1024 + threadIdx.x;
    int v = (i < N_NODES) ? g_deg_in[i] : 0;
    s[threadIdx.x] = v;
    __syncthreads();
    for (int off = 1; off < 1024; off <<= 1) {
        int t = (threadIdx.x >= off) ? s[threadIdx.x - off] : 0;
        __syncthreads();
        s[threadIdx.x] += t;
        __syncthreads();
    }
    if (i < N_NODES) g_incl[i] = s[threadIdx.x];
    if (threadIdx.x == 1023) g_blocksum[blockIdx.x] = s[1023];
}

__global__ void k_scan_tot(int nb) {
    __shared__ int s[256];
    int t = threadIdx.x;
    if (t < nb) s[t] = g_blocksum[t];
    __syncthreads();
    if (t == 0) {
        int run = 0;
        for (int b = 0; b < nb; b++) { int tmp = s[b]; s[b] = run; run += tmp; }
    }
    __syncthreads();
    if (t < nb) g_blocksum[t] = s[t];
}

__global__ void k_scan_fin() {
    int i = blockIdx.x * blockDim.x + threadIdx.x;
    if (i < N_NODES) {
        int incl = g_incl[i] + g_blocksum[i >> 10];
        g_incl[i] = incl;
        int di = g_deg_in[i], dout = g_deg_out[i];
        g_cursor[i] = incl - di;
        g_ns[i] = rsqrtf((float)(dout > 1 ? dout : 1));
        g_nd[i] = rsqrtf((float)(di   > 1 ? di   : 1));
    }
}

__global__ void k_fill(const int* __restrict__ src, const int* __restrict__ dst) {
    int e = blockIdx.x * blockDim.x + threadIdx.x;
    if (e < N_EDGES) {
        int pos = atomicAdd(&g_cursor[dst[e]], 1);
        g_csr[pos] = src[e];
    }
}

// ---------------- generic register-tiled SGEMM: out = (A * ns[row]) @ W ----------------
template <int BM, int BN, int BK, int TM, int TN>
__global__ void k_gemm(const float* __restrict__ A, const float* __restrict__ W,
                       const float* __restrict__ ns, float* __restrict__ out,
                       int M, int K, int Ncols, int ldo) {
    constexpr int NT = (BM / TM) * (BN / TN);
    __shared__ __align__(16) float As[BK][BM];
    __shared__ __align__(16) float Bs[BK][BN];

    int tid  = threadIdx.x;
    int tcol = tid % (BN / TN);
    int trow = tid / (BN / TN);
    int rowbase = blockIdx.y * BM;
    int colbase = blockIdx.x * BN;

    float acc[TM][TN];
#pragma unroll
    for (int i = 0; i < TM; i++)
#pragma unroll
        for (int j = 0; j < TN; j++) acc[i][j] = 0.f;

    for (int k0 = 0; k0 < K; k0 += BK) {
#pragma unroll
        for (int i = tid; i < BM * BK; i += NT) {
            int r = i / BK, c = i % BK;
            int gr = rowbase + r, gk = k0 + c;
            float v = 0.f;
            if (gr < M && gk < K) v = A[(long)gr * K + gk] * ns[gr];
            As[c][r] = v;
        }
#pragma unroll
        for (int i = tid; i < BK * BN; i += NT) {
            int r = i / BN, c = i % BN;
            int gk = k0 + r, gc = colbase + c;
            float v = 0.f;
            if (gk < K && gc < Ncols) v = W[(long)gk * Ncols + gc];
            Bs[r][c] = v;
        }
        __syncthreads();

#pragma unroll
        for (int kk = 0; kk < BK; kk++) {
            float ra[TM], rb[TN];
#pragma unroll
            for (int i = 0; i < TM; i += 4)
                *(float4*)&ra[i] = *(const float4*)&As[kk][trow * TM + i];
#pragma unroll
            for (int j = 0; j < TN; j += 4)
                *(float4*)&rb[j] = *(const float4*)&Bs[kk][tcol * TN + j];
#pragma unroll
            for (int i = 0; i < TM; i++)
#pragma unroll
                for (int j = 0; j < TN; j++)
                    acc[i][j] += ra[i] * rb[j];
        }
        __syncthreads();
    }

#pragma unroll
    for (int i = 0; i < TM; i++) {
        int gr = rowbase + trow * TM + i;
        if (gr >= M) continue;
#pragma unroll
        for (int j = 0; j < TN; j++) {
            int gc = colbase + tcol * TN + j;
            if (gc < Ncols) out[(long)gr * ldo + gc] = acc[i][j];
        }
    }
}

// ---------------- layer-1 aggregation: warp per node, gather, fuse nd+bias+relu ----------------
__global__ void k_agg1(const float* __restrict__ b1) {
    int warp = (blockIdx.x * blockDim.x + threadIdx.x) >> 5;
    int lane = threadIdx.x & 31;
    if (warp >= N_NODES) return;
    int end = g_incl[warp];
    int start = end - g_deg_in[warp];
    float4 acc = {0.f, 0.f, 0.f, 0.f};
    for (int j = start; j < end; j++) {
        int src = g_csr[j];
        float4 v = *((const float4*)(g_h1 + (long)src * HID) + lane);
        acc.x += v.x; acc.y += v.y; acc.z += v.z; acc.w += v.w;
    }
    float nd = g_nd[warp];
    float4 bb = ((const float4*)b1)[lane];
    float4 o;
    o.x = fmaxf(acc.x * nd + bb.x, 0.f);
    o.y = fmaxf(acc.y * nd + bb.y, 0.f);
    o.z = fmaxf(acc.z * nd + bb.z, 0.f);
    o.w = fmaxf(acc.w * nd + bb.w, 0.f);
    *((float4*)(g_h1b + (long)warp * HID) + lane) = o;
}

// ---------------- layer-2 aggregation: warp per node, fuse nd+bias, write d_out ----------------
__global__ void k_agg2(const float* __restrict__ b2, float* __restrict__ out) {
    int warp = (blockIdx.x * blockDim.x + threadIdx.x) >> 5;
    int lane = threadIdx.x & 31;
    if (warp >= N_NODES) return;
    int end = g_incl[warp];
    int start = end - g_deg_in[warp];
    float a0 = 0.f, a1 = 0.f;
    for (int j = start; j < end; j++) {
        int src = g_csr[j];
        const float* p = g_h2 + (long)src * NCLS;
        a0 += p[lane];
        if (lane < NCLS - 32) a1 += p[lane + 32];
    }
    float nd = g_nd[warp];
    float* po = out + (long)warp * NCLS;
    po[lane] = a0 * nd + b2[lane];
    if (lane < NCLS - 32) po[lane + 32] = a1 * nd + b2[lane + 32];
}

// ---------------- launcher ----------------
extern "C" void kernel_launch(void* const* d_in, const int* in_sizes, int n_in,
                              void* d_out, int out_size) {
    const float* x    = (const float*)d_in[0];
    const int*   esrc = (const int*)  d_in[1];
    const int*   edst = (const int*)  d_in[2];
    const float* W1   = (const float*)d_in[3];
    const float* b1   = (const float*)d_in[4];
    const float* W2   = (const float*)d_in[5];
    const float* b2   = (const float*)d_in[6];
    float*       out  = (float*)d_out;

    float *p_h1, *p_h1b, *p_h2, *p_ns;
    cudaGetSymbolAddress((void**)&p_h1,  g_h1);
    cudaGetSymbolAddress((void**)&p_h1b, g_h1b);
    cudaGetSymbolAddress((void**)&p_h2,  g_h2);
    cudaGetSymbolAddress((void**)&p_ns,  g_ns);

    const int TB = 256;
    // degrees + norms + CSR
    k_zero_deg<<<(N_NODES + TB - 1) / TB, TB>>>();
    k_count   <<<(N_EDGES + TB - 1) / TB, TB>>>(esrc, edst);
    int nb = (N_NODES + 1023) / 1024;
    k_scan_block<<<nb, 1024>>>();
    k_scan_tot  <<<1, 256>>>(nb);
    k_scan_fin  <<<(N_NODES + TB - 1) / TB, TB>>>();
    k_fill      <<<(N_EDGES + TB - 1) / TB, TB>>>(esrc, edst);

    // layer 1: GEMM (x*ns)@W1 -> h1 ; gather-agg + nd + b1 + relu -> h1b
    {
        dim3 grid(1, (N_NODES + 127) / 128);
        k_gemm<128, 128, 8, 8, 8><<<grid, 256>>>(x, W1, p_ns, p_h1,
                                                 N_NODES, NFEAT, HID, HID);
    }
    k_agg1<<<(N_NODES * 32 + TB - 1) / TB, TB>>>(b1);

    // layer 2: GEMM (h1b*ns)@W2 -> h2 ; gather-agg + nd + b2 -> out
    {
        dim3 grid(1, (N_NODES + 127) / 128);
        k_gemm<128, 64, 8, 8, 4><<<grid, 256>>>(p_h1b, W2, p_ns, p_h2,
                                                N_NODES, HID, NCLS, NCLS);
    }
    k_agg2<<<(N_NODES * 32 + TB - 1) / TB, TB>>>(b2, out);
}

// round 2
// speedup vs baseline: 3.5749x; 3.5749x over previous
#include <cuda_runtime.h>
#include <cuda_bf16.h>

#define N_NODES  100000
#define N_EDGES  1600000
#define NFEAT    602
#define HID      128
#define NCLS     41

// ---------------- device scratch (no allocations allowed) ----------------
__device__ int   g_deg_in[N_NODES];
__device__ int   g_deg_out[N_NODES];
__device__ float g_ns[N_NODES];          // deg_out^-1/2 (clipped)
__device__ float g_nd[N_NODES];          // deg_in^-1/2  (clipped)
__device__ int   g_incl[N_NODES];        // inclusive prefix sum of deg_in
__device__ int   g_blocksum[256];
__device__ int   g_cursor[N_NODES];
__device__ int   g_csr[N_EDGES];         // src ids grouped by dst
__device__ __align__(16) float g_h1 [(size_t)N_NODES * HID];
__device__ __align__(16) float g_h1b[(size_t)N_NODES * HID];
__device__ __align__(16) float g_h2 [(size_t)N_NODES * NCLS];

// ---------------- degree / norm / CSR build ----------------
__global__ void k_zero_deg() {
    int i = blockIdx.x * blockDim.x + threadIdx.x;
    if (i < N_NODES) { g_deg_in[i] = 0; g_deg_out[i] = 0; }
}

__global__ void k_count(const int* __restrict__ src, const int* __restrict__ dst) {
    int e = blockIdx.x * blockDim.x + threadIdx.x;
    if (e < N_EDGES) {
        atomicAdd(&g_deg_out[src[e]], 1);
        atomicAdd(&g_deg_in [dst[e]], 1);
    }
}

__global__ void k_scan_block() {
    __shared__ int s[1024];
    int i = blockIdx.x * 1024 + threadIdx.x;
    int v = (i < N_NODES) ? g_deg_in[i] : 0;
    s[threadIdx.x] = v;
    __syncthreads();
    for (int off = 1; off < 1024; off <<= 1) {
        int t = (threadIdx.x >= off) ? s[threadIdx.x - off] : 0;
        __syncthreads();
        s[threadIdx.x] += t;
        __syncthreads();
    }
    if (i < N_NODES) g_incl[i] = s[threadIdx.x];
    if (threadIdx.x == 1023) g_blocksum[blockIdx.x] = s[1023];
}

__global__ void k_scan_tot(int nb) {
    __shared__ int s[256];
    int t = threadIdx.x;
    if (t < nb) s[t] = g_blocksum[t];
    __syncthreads();
    if (t == 0) {
        int run = 0;
        for (int b = 0; b < nb; b++) { int tmp = s[b]; s[b] = run; run += tmp; }
    }
    __syncthreads();
    if (t < nb) g_blocksum[t] = s[t];
}

__global__ void k_scan_fin() {
    int i = blockIdx.x * blockDim.x + threadIdx.x;
    if (i < N_NODES) {
        int incl = g_incl[i] + g_blocksum[i >> 10];
        g_incl[i] = incl;
        int di = g_deg_in[i], dout = g_deg_out[i];
        g_cursor[i] = incl - di;
        g_ns[i] = rsqrtf((float)(dout > 1 ? dout : 1));
        g_nd[i] = rsqrtf((float)(di   > 1 ? di   : 1));
    }
}

__global__ void k_fill(const int* __restrict__ src, const int* __restrict__ dst) {
    int e = blockIdx.x * blockDim.x + threadIdx.x;
    if (e < N_EDGES) {
        int pos = atomicAdd(&g_cursor[dst[e]], 1);
        g_csr[pos] = src[e];
    }
}

// ---------------- tf32 tensor-core GEMM1: h1 = (x * ns[row]) @ W1 ----------------
// M=100000, K=602, N=128. BM=128, BN=128, BK=32. 256 threads, 8 warps (4x2),
// warp tile 32x64 via mma.sync.m16n8k8.tf32.

__device__ __forceinline__ unsigned f2tf32(float x) {
    unsigned r;
    asm("cvt.rna.tf32.f32 %0, %1;" : "=r"(r) : "f"(x));
    return r;
}

__global__ __launch_bounds__(256, 2)
void k_gemm1_tf32(const float* __restrict__ A, const float* __restrict__ W,
                  const float* __restrict__ ns, float* __restrict__ out, int M) {
    __shared__ float As[128][36];   // [m][k], stride 36 -> conflict-free frag loads
    __shared__ float Bs[32][136];   // [k][n], stride 136 -> conflict-free frag loads

    const int tid  = threadIdx.x;
    const int lane = tid & 31;
    const int w    = tid >> 5;
    const int wm   = w >> 1;          // 0..3 -> m offset wm*32
    const int wn   = w & 1;           // 0..1 -> n offset wn*64
    const int g    = lane >> 2;       // groupID  0..7
    const int tig  = lane & 3;        // thread-in-group 0..3
    const int rowbase = blockIdx.y * 128;

    float acc[2][8][4];
#pragma unroll
    for (int mi = 0; mi < 2; mi++)
#pragma unroll
        for (int ni = 0; ni < 8; ni++)
#pragma unroll
            for (int j = 0; j < 4; j++) acc[mi][ni][j] = 0.f;

    float2 ra[8];
    float4 rb[4];

    // A: 128 rows x 32 k as 2048 float2 (row stride 602 floats = 8B aligned only)
    auto loadA = [&](int k0) {
#pragma unroll
        for (int i = 0; i < 8; i++) {
            int idx = tid + i * 256;
            int m = idx & 127, kq2 = idx >> 7;      // kq2 0..15
            int k = k0 + kq2 * 2;
            int gm = rowbase + m;
            float2 v = make_float2(0.f, 0.f);
            if (gm < M && k < NFEAT) {              // NFEAT even, k even -> k+1 ok
                v = *(const float2*)(A + (long)gm * NFEAT + k);
                float s = ns[gm];
                v.x *= s; v.y *= s;
            }
            ra[i] = v;
        }
    };
    auto stsA = [&]() {
#pragma unroll
        for (int i = 0; i < 8; i++) {
            int idx = tid + i * 256;
            int m = idx & 127, kq2 = idx >> 7;
            As[m][kq2 * 2]     = __uint_as_float(f2tf32(ra[i].x));
            As[m][kq2 * 2 + 1] = __uint_as_float(f2tf32(ra[i].y));
        }
    };
    // B: 32 k-rows x 128 n as 1024 float4 (row stride 128 floats, 16B aligned)
    auto loadB = [&](int k0) {
#pragma unroll
        for (int i = 0; i < 4; i++) {
            int idx = tid + i * 256;
            int n4 = idx & 31, k = idx >> 5;        // k 0..31
            float4 v = make_float4(0.f, 0.f, 0.f, 0.f);
            if (k0 + k < NFEAT) v = *(const float4*)(W + (long)(k0 + k) * 128 + n4 * 4);
            rb[i] = v;
        }
    };
    auto stsB = [&]() {
#pragma unroll
        for (int i = 0; i < 4; i++) {
            int idx = tid + i * 256;
            int n4 = idx & 31, k = idx >> 5;
            Bs[k][n4 * 4]     = __uint_as_float(f2tf32(rb[i].x));
            Bs[k][n4 * 4 + 1] = __uint_as_float(f2tf32(rb[i].y));
            Bs[k][n4 * 4 + 2] = __uint_as_float(f2tf32(rb[i].z));
            Bs[k][n4 * 4 + 3] = __uint_as_float(f2tf32(rb[i].w));
        }
    };

    const int NIT = (NFEAT + 31) / 32;   // 19

    loadA(0); loadB(0);
    stsA();  stsB();
    __syncthreads();

    for (int it = 0; it < NIT; it++) {
        if (it + 1 < NIT) { loadA((it + 1) * 32); loadB((it + 1) * 32); }

#pragma unroll
        for (int kk = 0; kk < 32; kk += 8) {
            unsigned afr[2][4];
#pragma unroll
            for (int mi = 0; mi < 2; mi++) {
                int mb = wm * 32 + mi * 16;
                afr[mi][0] = __float_as_uint(As[mb + g    ][kk + tig    ]);
                afr[mi][1] = __float_as_uint(As[mb + g + 8][kk + tig    ]);
                afr[mi][2] = __float_as_uint(As[mb + g    ][kk + tig + 4]);
                afr[mi][3] = __float_as_uint(As[mb + g + 8][kk + tig + 4]);
            }
            unsigned bfr[8][2];
#pragma unroll
            for (int ni = 0; ni < 8; ni++) {
                int nb = wn * 64 + ni * 8;
                bfr[ni][0] = __float_as_uint(Bs[kk + tig    ][nb + g]);
                bfr[ni][1] = __float_as_uint(Bs[kk + tig + 4][nb + g]);
            }
#pragma unroll
            for (int mi = 0; mi < 2; mi++)
#pragma unroll
                for (int ni = 0; ni < 8; ni++) {
                    asm volatile(
                        "mma.sync.aligned.m16n8k8.row.col.f32.tf32.tf32.f32 "
                        "{%0,%1,%2,%3}, {%4,%5,%6,%7}, {%8,%9}, {%0,%1,%2,%3};"
                        : "+f"(acc[mi][ni][0]), "+f"(acc[mi][ni][1]),
                          "+f"(acc[mi][ni][2]), "+f"(acc[mi][ni][3])
                        : "r"(afr[mi][0]), "r"(afr[mi][1]),
                          "r"(afr[mi][2]), "r"(afr[mi][3]),
                          "r"(bfr[ni][0]), "r"(bfr[ni][1]));
                }
        }
        __syncthreads();
        if (it + 1 < NIT) {
            stsA(); stsB();
            __syncthreads();
        }
    }

    // epilogue: c0/c1 at (row g, col 2tig/2tig+1), c2/c3 at row g+8
#pragma unroll
    for (int mi = 0; mi < 2; mi++) {
#pragma unroll
        for (int ni = 0; ni < 8; ni++) {
            int col  = wn * 64 + ni * 8 + tig * 2;
            int row0 = rowbase + wm * 32 + mi * 16 + g;
            int row1 = row0 + 8;
            if (row0 < M)
                *(float2*)(out + (long)row0 * 128 + col) =
                    make_float2(acc[mi][ni][0], acc[mi][ni][1]);
            if (row1 < M)
                *(float2*)(out + (long)row1 * 128 + col) =
                    make_float2(acc[mi][ni][2], acc[mi][ni][3]);
        }
    }
}

// ---------------- fp32 register-tiled SGEMM (layer 2): out = (A * ns[row]) @ W ----------------
template <int BM, int BN, int BK, int TM, int TN>
__global__ void k_gemm(const float* __restrict__ A, const float* __restrict__ W,
                       const float* __restrict__ ns, float* __restrict__ out,
                       int M, int K, int Ncols, int ldo) {
    constexpr int NT = (BM / TM) * (BN / TN);
    __shared__ __align__(16) float As[BK][BM];
    __shared__ __align__(16) float Bs[BK][BN];

    int tid  = threadIdx.x;
    int tcol = tid % (BN / TN);
    int trow = tid / (BN / TN);
    int rowbase = blockIdx.y * BM;
    int colbase = blockIdx.x * BN;

    float acc[TM][TN];
#pragma unroll
    for (int i = 0; i < TM; i++)
#pragma unroll
        for (int j = 0; j < TN; j++) acc[i][j] = 0.f;

    for (int k0 = 0; k0 < K; k0 += BK) {
#pragma unroll
        for (int i = tid; i < BM * BK; i += NT) {
            int r = i / BK, c = i % BK;
            int gr = rowbase + r, gk = k0 + c;
            float v = 0.f;
            if (gr < M && gk < K) v = A[(long)gr * K + gk] * ns[gr];
            As[c][r] = v;
        }
#pragma unroll
        for (int i = tid; i < BK * BN; i += NT) {
            int r = i / BN, c = i % BN;
            int gk = k0 + r, gc = colbase + c;
            float v = 0.f;
            if (gk < K && gc < Ncols) v = W[(long)gk * Ncols + gc];
            Bs[r][c] = v;
        }
        __syncthreads();

#pragma unroll
        for (int kk = 0; kk < BK; kk++) {
            float rav[TM], rbv[TN];
#pragma unroll
            for (int i = 0; i < TM; i += 4)
                *(float4*)&rav[i] = *(const float4*)&As[kk][trow * TM + i];
#pragma unroll
            for (int j = 0; j < TN; j += 4)
                *(float4*)&rbv[j] = *(const float4*)&Bs[kk][tcol * TN + j];
#pragma unroll
            for (int i = 0; i < TM; i++)
#pragma unroll
                for (int j = 0; j < TN; j++)
                    acc[i][j] += rav[i] * rbv[j];
        }
        __syncthreads();
    }

#pragma unroll
    for (int i = 0; i < TM; i++) {
        int gr = rowbase + trow * TM + i;
        if (gr >= M) continue;
#pragma unroll
        for (int j = 0; j < TN; j++) {
            int gc = colbase + tcol * TN + j;
            if (gc < Ncols) out[(long)gr * ldo + gc] = acc[i][j];
        }
    }
}

// ---------------- layer-1 aggregation: warp per node, gather, fuse nd+bias+relu ----------------
__global__ void k_agg1(const float* __restrict__ b1) {
    int warp = (blockIdx.x * blockDim.x + threadIdx.x) >> 5;
    int lane = threadIdx.x & 31;
    if (warp >= N_NODES) return;
    int end = g_incl[warp];
    int start = end - g_deg_in[warp];
    float4 acc = {0.f, 0.f, 0.f, 0.f};
    for (int j = start; j < end; j++) {
        int src = g_csr[j];
        float4 v = *((const float4*)(g_h1 + (long)src * HID) + lane);
        acc.x += v.x; acc.y += v.y; acc.z += v.z; acc.w += v.w;
    }
    float nd = g_nd[warp];
    float4 bb = ((const float4*)b1)[lane];
    float4 o;
    o.x = fmaxf(acc.x * nd + bb.x, 0.f);
    o.y = fmaxf(acc.y * nd + bb.y, 0.f);
    o.z = fmaxf(acc.z * nd + bb.z, 0.f);
    o.w = fmaxf(acc.w * nd + bb.w, 0.f);
    *((float4*)(g_h1b + (long)warp * HID) + lane) = o;
}

// ---------------- layer-2 aggregation: warp per node, fuse nd+bias, write d_out ----------------
__global__ void k_agg2(const float* __restrict__ b2, float* __restrict__ out) {
    int warp = (blockIdx.x * blockDim.x + threadIdx.x) >> 5;
    int lane = threadIdx.x & 31;
    if (warp >= N_NODES) return;
    int end = g_incl[warp];
    int start = end - g_deg_in[warp];
    float a0 = 0.f, a1 = 0.f;
    for (int j = start; j < end; j++) {
        int src = g_csr[j];
        const float* p = g_h2 + (long)src * NCLS;
        a0 += p[lane];
        if (lane < NCLS - 32) a1 += p[lane + 32];
    }
    float nd = g_nd[warp];
    float* po = out + (long)warp * NCLS;
    po[lane] = a0 * nd + b2[lane];
    if (lane < NCLS - 32) po[lane + 32] = a1 * nd + b2[lane + 32];
}

// ---------------- launcher ----------------
extern "C" void kernel_launch(void* const* d_in, const int* in_sizes, int n_in,
                              void* d_out, int out_size) {
    const float* x    = (const float*)d_in[0];
    const int*   esrc = (const int*)  d_in[1];
    const int*   edst = (const int*)  d_in[2];
    const float* W1   = (const float*)d_in[3];
    const float* b1   = (const float*)d_in[4];
    const float* W2   = (const float*)d_in[5];
    const float* b2   = (const float*)d_in[6];
    float*       out  = (float*)d_out;

    float *p_h1, *p_h1b, *p_h2, *p_ns;
    cudaGetSymbolAddress((void**)&p_h1,  g_h1);
    cudaGetSymbolAddress((void**)&p_h1b, g_h1b);
    cudaGetSymbolAddress((void**)&p_h2,  g_h2);
    cudaGetSymbolAddress((void**)&p_ns,  g_ns);

    const int TB = 256;
    // degrees + norms + CSR
    k_zero_deg<<<(N_NODES + TB - 1) / TB, TB>>>();
    k_count   <<<(N_EDGES + TB - 1) / TB, TB>>>(esrc, edst);
    int nb = (N_NODES + 1023) / 1024;
    k_scan_block<<<nb, 1024>>>();
    k_scan_tot  <<<1, 256>>>(nb);
    k_scan_fin  <<<(N_NODES + TB - 1) / TB, TB>>>();
    k_fill      <<<(N_EDGES + TB - 1) / TB, TB>>>(esrc, edst);

    // layer 1: tf32 tensor GEMM (x*ns)@W1 -> h1 ; gather-agg + nd + b1 + relu -> h1b
    {
        dim3 grid(1, (N_NODES + 127) / 128);
        k_gemm1_tf32<<<grid, 256>>>(x, W1, p_ns, p_h1, N_NODES);
    }
    k_agg1<<<(N_NODES * 32 + TB - 1) / TB, TB>>>(b1);

    // layer 2 (fp32 to protect error budget): (h1b*ns)@W2 -> h2 ; agg + nd + b2 -> out
    {
        dim3 grid(1, (N_NODES + 127) / 128);
        k_gemm<128, 64, 8, 8, 4><<<grid, 256>>>(p_h1b, W2, p_ns, p_h2,
                                                N_NODES, HID, NCLS, NCLS);
    }
    k_agg2<<<(N_NODES * 32 + TB - 1) / TB, TB>>>(b2, out);
}

// round 3
// speedup vs baseline: 5.0736x; 1.4192x over previous
#include <cuda_runtime.h>
#include <cuda_bf16.h>

#define N_NODES  100000
#define N_EDGES  1600000
#define NFEAT    602
#define HID      128
#define NCLS     41
#define H2S      42      // padded h2 row stride (col 41 = padding)

// ---------------- device scratch (no allocations allowed) ----------------
__device__ int   g_deg_in[N_NODES];
__device__ int   g_deg_out[N_NODES];
__device__ float g_ns[N_NODES];          // deg_out^-1/2 (clipped)
__device__ float g_nd[N_NODES];          // deg_in^-1/2  (clipped)
__device__ int   g_incl[N_NODES];        // inclusive prefix sum of deg_in
__device__ int   g_blocksum[256];
__device__ int   g_cursor[N_NODES];
__device__ int   g_csr[N_EDGES];         // src ids grouped by dst
__device__ __align__(16) float g_h1 [(size_t)N_NODES * HID];
__device__ __align__(16) float g_h1b[(size_t)N_NODES * HID];
__device__ __align__(16) float g_h2 [(size_t)N_NODES * H2S];

// ---------------- cp.async helpers ----------------
__device__ __forceinline__ void cp_async4(void* dst, const void* src, int ssize) {
    asm volatile("cp.async.ca.shared.global [%0], [%1], 4, %2;\n" ::
        "r"((unsigned)__cvta_generic_to_shared(dst)), "l"(src), "r"(ssize));
}
__device__ __forceinline__ void cp_async8(void* dst, const void* src, int ssize) {
    asm volatile("cp.async.ca.shared.global [%0], [%1], 8, %2;\n" ::
        "r"((unsigned)__cvta_generic_to_shared(dst)), "l"(src), "r"(ssize));
}
__device__ __forceinline__ void cp_async16(void* dst, const void* src, int ssize) {
    asm volatile("cp.async.cg.shared.global [%0], [%1], 16, %2;\n" ::
        "r"((unsigned)__cvta_generic_to_shared(dst)), "l"(src), "r"(ssize));
}
__device__ __forceinline__ void cp_commit() {
    asm volatile("cp.async.commit_group;\n" ::: "memory");
}
__device__ __forceinline__ void cp_wait_all() {
    asm volatile("cp.async.wait_group 0;\n" ::: "memory");
}

__device__ __forceinline__ unsigned f2tf32(float x) {
    unsigned r;
    asm("cvt.rna.tf32.f32 %0, %1;" : "=r"(r) : "f"(x));
    return r;
}

// ---------------- degree / norm / CSR build ----------------
__global__ void k_zero_deg() {
    int i = blockIdx.x * blockDim.x + threadIdx.x;
    if (i < N_NODES) { g_deg_in[i] = 0; g_deg_out[i] = 0; }
}

__global__ void k_count(const int* __restrict__ src, const int* __restrict__ dst) {
    int e = blockIdx.x * blockDim.x + threadIdx.x;
    if (e < N_EDGES) {
        atomicAdd(&g_deg_out[src[e]], 1);
        atomicAdd(&g_deg_in [dst[e]], 1);
    }
}

__global__ void k_scan_block() {
    __shared__ int s[1024];
    int i = blockIdx.x * 1024 + threadIdx.x;
    int v = (i < N_NODES) ? g_deg_in[i] : 0;
    s[threadIdx.x] = v;
    __syncthreads();
    for (int off = 1; off < 1024; off <<= 1) {
        int t = (threadIdx.x >= off) ? s[threadIdx.x - off] : 0;
        __syncthreads();
        s[threadIdx.x] += t;
        __syncthreads();
    }
    if (i < N_NODES) g_incl[i] = s[threadIdx.x];
    if (threadIdx.x == 1023) g_blocksum[blockIdx.x] = s[1023];
}

__global__ void k_scan_tot(int nb) {
    __shared__ int s[256];
    int t = threadIdx.x;
    if (t < nb) s[t] = g_blocksum[t];
    __syncthreads();
    if (t == 0) {
        int run = 0;
        for (int b = 0; b < nb; b++) { int tmp = s[b]; s[b] = run; run += tmp; }
    }
    __syncthreads();
    if (t < nb) g_blocksum[t] = s[t];
}

__global__ void k_scan_fin() {
    int i = blockIdx.x * blockDim.x + threadIdx.x;
    if (i < N_NODES) {
        int incl = g_incl[i] + g_blocksum[i >> 10];
        g_incl[i] = incl;
        int di = g_deg_in[i], dout = g_deg_out[i];
        g_cursor[i] = incl - di;
        g_ns[i] = rsqrtf((float)(dout > 1 ? dout : 1));
        g_nd[i] = rsqrtf((float)(di   > 1 ? di   : 1));
    }
}

__global__ void k_fill(const int* __restrict__ src, const int* __restrict__ dst) {
    int e = blockIdx.x * blockDim.x + threadIdx.x;
    if (e < N_EDGES) {
        int pos = atomicAdd(&g_cursor[dst[e]], 1);
        g_csr[pos] = src[e];
    }
}

// ---------------- GEMM1 tf32: h1 = ns[row] * (x @ W1)  (128x128 tile, cp.async) ----------------
__global__ __launch_bounds__(256, 2)
void k_gemm1_tf32(const float* __restrict__ A, const float* __restrict__ W,
                  const float* __restrict__ ns, float* __restrict__ out, int M) {
    __shared__ float As[2][128][36];
    __shared__ float Bs[2][32][136];

    const int tid  = threadIdx.x;
    const int lane = tid & 31;
    const int w    = tid >> 5;
    const int wm   = w >> 1;
    const int wn   = w & 1;
    const int g    = lane >> 2;
    const int tig  = lane & 3;
    const int rowbase = blockIdx.y * 128;

    float acc[2][8][4];
#pragma unroll
    for (int mi = 0; mi < 2; mi++)
#pragma unroll
        for (int ni = 0; ni < 8; ni++)
#pragma unroll
            for (int j = 0; j < 4; j++) acc[mi][ni][j] = 0.f;

    auto issueA = [&](int k0, int b) {
#pragma unroll
        for (int i = 0; i < 8; i++) {
            int idx = tid + i * 256;
            int m = idx & 127, kq2 = idx >> 7;        // kq2 0..15
            int k = k0 + kq2 * 2;
            int gm = rowbase + m;
            int valid = (gm < M) && (k < NFEAT);
            const float* src = A + (valid ? ((long)gm * NFEAT + k) : 0);
            cp_async8(&As[b][m][kq2 * 2], src, valid ? 8 : 0);
        }
    };
    auto issueB = [&](int k0, int b) {
#pragma unroll
        for (int i = 0; i < 4; i++) {
            int idx = tid + i * 256;
            int n4 = idx & 31, k = idx >> 5;          // k 0..31
            int valid = (k0 + k) < NFEAT;
            const float* src = W + (valid ? ((long)(k0 + k) * 128 + n4 * 4) : 0);
            cp_async16(&Bs[b][k][n4 * 4], src, valid ? 16 : 0);
        }
    };

    const int NIT = (NFEAT + 31) / 32;   // 19

    issueA(0, 0); issueB(0, 0); cp_commit();

    for (int it = 0; it < NIT; it++) {
        const int cur = it & 1;
        cp_wait_all();
        __syncthreads();
        if (it + 1 < NIT) {
            issueA((it + 1) * 32, cur ^ 1);
            issueB((it + 1) * 32, cur ^ 1);
            cp_commit();
        }

#pragma unroll
        for (int kk = 0; kk < 32; kk += 8) {
            unsigned afr[2][4];
#pragma unroll
            for (int mi = 0; mi < 2; mi++) {
                int mb = wm * 32 + mi * 16;
                afr[mi][0] = f2tf32(As[cur][mb + g    ][kk + tig    ]);
                afr[mi][1] = f2tf32(As[cur][mb + g + 8][kk + tig    ]);
                afr[mi][2] = f2tf32(As[cur][mb + g    ][kk + tig + 4]);
                afr[mi][3] = f2tf32(As[cur][mb + g + 8][kk + tig + 4]);
            }
            unsigned bfr[8][2];
#pragma unroll
            for (int ni = 0; ni < 8; ni++) {
                int nb = wn * 64 + ni * 8;
                bfr[ni][0] = f2tf32(Bs[cur][kk + tig    ][nb + g]);
                bfr[ni][1] = f2tf32(Bs[cur][kk + tig + 4][nb + g]);
            }
#pragma unroll
            for (int mi = 0; mi < 2; mi++)
#pragma unroll
                for (int ni = 0; ni < 8; ni++) {
                    asm volatile(
                        "mma.sync.aligned.m16n8k8.row.col.f32.tf32.tf32.f32 "
                        "{%0,%1,%2,%3}, {%4,%5,%6,%7}, {%8,%9}, {%0,%1,%2,%3};"
                        : "+f"(acc[mi][ni][0]), "+f"(acc[mi][ni][1]),
                          "+f"(acc[mi][ni][2]), "+f"(acc[mi][ni][3])
                        : "r"(afr[mi][0]), "r"(afr[mi][1]),
                          "r"(afr[mi][2]), "r"(afr[mi][3]),
                          "r"(bfr[ni][0]), "r"(bfr[ni][1]));
                }
        }
    }

    // epilogue: ns applied here (row scaling commutes with GEMM)
#pragma unroll
    for (int mi = 0; mi < 2; mi++) {
        int row0 = rowbase + wm * 32 + mi * 16 + g;
        int row1 = row0 + 8;
        float s0 = (row0 < M) ? ns[row0] : 0.f;
        float s1 = (row1 < M) ? ns[row1] : 0.f;
#pragma unroll
        for (int ni = 0; ni < 8; ni++) {
            int col = wn * 64 + ni * 8 + tig * 2;
            if (row0 < M)
                *(float2*)(out + (long)row0 * 128 + col) =
                    make_float2(acc[mi][ni][0] * s0, acc[mi][ni][1] * s0);
            if (row1 < M)
                *(float2*)(out + (long)row1 * 128 + col) =
                    make_float2(acc[mi][ni][2] * s1, acc[mi][ni][3] * s1);
        }
    }
}

// ---------------- GEMM2 tf32: h2 = ns[row] * (h1b @ W2)  (128x64 tile) ----------------
__global__ __launch_bounds__(256, 2)
void k_gemm2_tf32(const float* __restrict__ A, const float* __restrict__ W,
                  const float* __restrict__ ns, float* __restrict__ out, int M) {
    __shared__ float As[2][128][36];
    __shared__ float Bs[2][32][72];

    const int tid  = threadIdx.x;
    const int lane = tid & 31;
    const int w    = tid >> 5;
    const int wm   = w >> 1;
    const int wn   = w & 1;
    const int g    = lane >> 2;
    const int tig  = lane & 3;
    const int rowbase = blockIdx.y * 128;

    float acc[2][4][4];
#pragma unroll
    for (int mi = 0; mi < 2; mi++)
#pragma unroll
        for (int ni = 0; ni < 4; ni++)
#pragma unroll
            for (int j = 0; j < 4; j++) acc[mi][ni][j] = 0.f;

    auto issueA = [&](int k0, int b) {
#pragma unroll
        for (int i = 0; i < 4; i++) {
            int idx = tid + i * 256;                  // 0..1023
            int m = idx >> 3, kq4 = idx & 7;
            int gm = rowbase + m;
            int valid = (gm < M);
            const float* src = A + (valid ? ((long)gm * HID + k0 + kq4 * 4) : 0);
            cp_async16(&As[b][m][kq4 * 4], src, valid ? 16 : 0);
        }
    };
    auto issueB = [&](int k0, int b) {
#pragma unroll
        for (int i = 0; i < 8; i++) {
            int idx = tid + i * 256;                  // 0..2047
            int k = idx >> 6, n = idx & 63;
            int valid = (n < NCLS);
            const float* src = W + (valid ? ((long)(k0 + k) * NCLS + n) : 0);
            cp_async4(&Bs[b][k][n], src, valid ? 4 : 0);
        }
    };

    const int NIT = HID / 32;   // 4

    issueA(0, 0); issueB(0, 0); cp_commit();

    for (int it = 0; it < NIT; it++) {
        const int cur = it & 1;
        cp_wait_all();
        __syncthreads();
        if (it + 1 < NIT) {
            issueA((it + 1) * 32, cur ^ 1);
            issueB((it + 1) * 32, cur ^ 1);
            cp_commit();
        }

#pragma unroll
        for (int kk = 0; kk < 32; kk += 8) {
            unsigned afr[2][4];
#pragma unroll
            for (int mi = 0; mi < 2; mi++) {
                int mb = wm * 32 + mi * 16;
                afr[mi][0] = f2tf32(As[cur][mb + g    ][kk + tig    ]);
                afr[mi][1] = f2tf32(As[cur][mb + g + 8][kk + tig    ]);
                afr[mi][2] = f2tf32(As[cur][mb + g    ][kk + tig + 4]);
                afr[mi][3] = f2tf32(As[cur][mb + g + 8][kk + tig + 4]);
            }
            unsigned bfr[4][2];
#pragma unroll
            for (int ni = 0; ni < 4; ni++) {
                int nb = wn * 32 + ni * 8;
                bfr[ni][0] = f2tf32(Bs[cur][kk + tig    ][nb + g]);
                bfr[ni][1] = f2tf32(Bs[cur][kk + tig + 4][nb + g]);
            }
#pragma unroll
            for (int mi = 0; mi < 2; mi++)
#pragma unroll
                for (int ni = 0; ni < 4; ni++) {
                    asm volatile(
                        "mma.sync.aligned.m16n8k8.row.col.f32.tf32.tf32.f32 "
                        "{%0,%1,%2,%3}, {%4,%5,%6,%7}, {%8,%9}, {%0,%1,%2,%3};"
                        : "+f"(acc[mi][ni][0]), "+f"(acc[mi][ni][1]),
                          "+f"(acc[mi][ni][2]), "+f"(acc[mi][ni][3])
                        : "r"(afr[mi][0]), "r"(afr[mi][1]),
                          "r"(afr[mi][2]), "r"(afr[mi][3]),
                          "r"(bfr[ni][0]), "r"(bfr[ni][1]));
                }
        }
    }

#pragma unroll
    for (int mi = 0; mi < 2; mi++) {
        int row0 = rowbase + wm * 32 + mi * 16 + g;
        int row1 = row0 + 8;
        float s0 = (row0 < M) ? ns[row0] : 0.f;
        float s1 = (row1 < M) ? ns[row1] : 0.f;
#pragma unroll
        for (int ni = 0; ni < 4; ni++) {
            int col = wn * 32 + ni * 8 + tig * 2;
            if (col <= 40) {                          // col 40 pair writes pad col 41
                if (row0 < M)
                    *(float2*)(out + (long)row0 * H2S + col) =
                        make_float2(acc[mi][ni][0] * s0, acc[mi][ni][1] * s0);
                if (row1 < M)
                    *(float2*)(out + (long)row1 * H2S + col) =
                        make_float2(acc[mi][ni][2] * s1, acc[mi][ni][3] * s1);
            }
        }
    }
}

// ---------------- layer-1 aggregation: warp/node gather, unroll-4, fuse nd+bias+relu ----------------
__global__ void k_agg1(const float* __restrict__ b1) {
    int node = (blockIdx.x * blockDim.x + threadIdx.x) >> 5;
    int lane = threadIdx.x & 31;
    if (node >= N_NODES) return;
    int end = g_incl[node];
    int j = end - g_deg_in[node];
    float4 acc = {0.f, 0.f, 0.f, 0.f};
    for (; j + 4 <= end; j += 4) {
        int s0 = g_csr[j], s1 = g_csr[j + 1], s2 = g_csr[j + 2], s3 = g_csr[j + 3];
        float4 v0 = *((const float4*)(g_h1 + (long)s0 * HID) + lane);
        float4 v1 = *((const float4*)(g_h1 + (long)s1 * HID) + lane);
        float4 v2 = *((const float4*)(g_h1 + (long)s2 * HID) + lane);
        float4 v3 = *((const float4*)(g_h1 + (long)s3 * HID) + lane);
        acc.x += v0.x + v1.x + v2.x + v3.x;
        acc.y += v0.y + v1.y + v2.y + v3.y;
        acc.z += v0.z + v1.z + v2.z + v3.z;
        acc.w += v0.w + v1.w + v2.w + v3.w;
    }
    for (; j < end; j++) {
        int s = g_csr[j];
        float4 v = *((const float4*)(g_h1 + (long)s * HID) + lane);
        acc.x += v.x; acc.y += v.y; acc.z += v.z; acc.w += v.w;
    }
    float nd = g_nd[node];
    float4 bb = ((const float4*)b1)[lane];
    float4 o;
    o.x = fmaxf(acc.x * nd + bb.x, 0.f);
    o.y = fmaxf(acc.y * nd + bb.y, 0.f);
    o.z = fmaxf(acc.z * nd + bb.z, 0.f);
    o.w = fmaxf(acc.w * nd + bb.w, 0.f);
    *((float4*)(g_h1b + (long)node * HID) + lane) = o;
}

// ---------------- layer-2 aggregation: warp/node gather, unroll-4, fuse nd+bias ----------------
__global__ void k_agg2(const float* __restrict__ b2, float* __restrict__ out) {
    int node = (blockIdx.x * blockDim.x + threadIdx.x) >> 5;
    int lane = threadIdx.x & 31;
    if (node >= N_NODES) return;
    int end = g_incl[node];
    int j = end - g_deg_in[node];
    float a0 = 0.f, a1 = 0.f;
    bool hi = lane < (NCLS - 32);
    for (; j + 4 <= end; j += 4) {
        int s0 = g_csr[j], s1 = g_csr[j + 1], s2 = g_csr[j + 2], s3 = g_csr[j + 3];
        const float* p0 = g_h2 + (long)s0 * H2S;
        const float* p1 = g_h2 + (long)s1 * H2S;
        const float* p2 = g_h2 + (long)s2 * H2S;
        const float* p3 = g_h2 + (long)s3 * H2S;
        a0 += p0[lane] + p1[lane] + p2[lane] + p3[lane];
        if (hi) a1 += p0[lane + 32] + p1[lane + 32] + p2[lane + 32] + p3[lane + 32];
    }
    for (; j < end; j++) {
        const float* p = g_h2 + (long)g_csr[j] * H2S;
        a0 += p[lane];
        if (hi) a1 += p[lane + 32];
    }
    float nd = g_nd[node];
    float* po = out + (long)node * NCLS;
    po[lane] = a0 * nd + b2[lane];
    if (hi) po[lane + 32] = a1 * nd + b2[lane + 32];
}

// ---------------- launcher ----------------
extern "C" void kernel_launch(void* const* d_in, const int* in_sizes, int n_in,
                              void* d_out, int out_size) {
    const float* x    = (const float*)d_in[0];
    const int*   esrc = (const int*)  d_in[1];
    const int*   edst = (const int*)  d_in[2];
    const float* W1   = (const float*)d_in[3];
    const float* b1   = (const float*)d_in[4];
    const float* W2   = (const float*)d_in[5];
    const float* b2   = (const float*)d_in[6];
    float*       out  = (float*)d_out;

    float *p_h1, *p_h1b, *p_h2, *p_ns;
    cudaGetSymbolAddress((void**)&p_h1,  g_h1);
    cudaGetSymbolAddress((void**)&p_h1b, g_h1b);
    cudaGetSymbolAddress((void**)&p_h2,  g_h2);
    cudaGetSymbolAddress((void**)&p_ns,  g_ns);

    const int TB = 256;
    // degrees + norms + CSR
    k_zero_deg<<<(N_NODES + TB - 1) / TB, TB>>>();
    k_count   <<<(N_EDGES + TB - 1) / TB, TB>>>(esrc, edst);
    int nb = (N_NODES + 1023) / 1024;
    k_scan_block<<<nb, 1024>>>();
    k_scan_tot  <<<1, 256>>>(nb);
    k_scan_fin  <<<(N_NODES + TB - 1) / TB, TB>>>();
    k_fill      <<<(N_EDGES + TB - 1) / TB, TB>>>(esrc, edst);

    // layer 1: tf32 GEMM -> h1 ; gather-agg + nd + b1 + relu -> h1b
    {
        dim3 grid(1, (N_NODES + 127) / 128);
        k_gemm1_tf32<<<grid, 256>>>(x, W1, p_ns, p_h1, N_NODES);
    }
    k_agg1<<<(N_NODES * 32 + TB - 1) / TB, TB>>>(b1);

    // layer 2: tf32 GEMM -> h2 (stride 42) ; gather-agg + nd + b2 -> out
    {
        dim3 grid(1, (N_NODES + 127) / 128);
        k_gemm2_tf32<<<grid, 256>>>(p_h1b, W2, p_ns, p_h2, N_NODES);
    }
    k_agg2<<<(N_NODES * 32 + TB - 1) / TB, TB>>>(b2, out);
}

// round 5
// speedup vs baseline: 5.6516x; 1.1139x over previous
#include <cuda_runtime.h>
#include <cuda_fp16.h>
#include <cuda_bf16.h>

#define N_NODES  100000
#define N_EDGES  1600000
#define NFEAT    602
#define HID      128
#define NCLS     41
#define H2S      48      // padded h2 row stride in halves (cols 41..47 pad)

// ---------------- device scratch (no allocations allowed) ----------------
__device__ int   g_deg_in[N_NODES];
__device__ int   g_deg_out[N_NODES];
__device__ float g_ns[N_NODES];          // deg_out^-1/2 (clipped)
__device__ float g_nd[N_NODES];          // deg_in^-1/2  (clipped)
__device__ int   g_incl[N_NODES];        // inclusive prefix sum of deg_in
__device__ int   g_blocksum[256];
__device__ int   g_cursor[N_NODES];
__device__ int   g_csr[N_EDGES];         // src ids grouped by dst
__device__ __align__(16) __half g_h1h[(size_t)N_NODES * HID];   // raw x@W1 (no ns), fp16
__device__ __align__(16) float  g_h1b[(size_t)N_NODES * HID];   // relu'd layer-1 output
__device__ __align__(16) __half g_h2h[(size_t)N_NODES * H2S];   // ns*(h1b@W2), fp16

// ---------------- streams/events for fork-join (created before harness baseline) ----
static cudaStream_t g_s2;
static cudaEvent_t  g_ev_fork, g_ev_join;
namespace {
struct StreamInit {
    StreamInit() {
        cudaStreamCreateWithFlags(&g_s2, cudaStreamNonBlocking);
        cudaEventCreateWithFlags(&g_ev_fork, cudaEventDisableTiming);
        cudaEventCreateWithFlags(&g_ev_join, cudaEventDisableTiming);
    }
};
StreamInit g_stream_init;
}

// ---------------- cp.async helpers ----------------
__device__ __forceinline__ void cp_async4(void* dst, const void* src, int ssize) {
    asm volatile("cp.async.ca.shared.global [%0], [%1], 4, %2;\n" ::
        "r"((unsigned)__cvta_generic_to_shared(dst)), "l"(src), "r"(ssize));
}
__device__ __forceinline__ void cp_async8(void* dst, const void* src, int ssize) {
    asm volatile("cp.async.ca.shared.global [%0], [%1], 8, %2;\n" ::
        "r"((unsigned)__cvta_generic_to_shared(dst)), "l"(src), "r"(ssize));
}
__device__ __forceinline__ void cp_async16(void* dst, const void* src, int ssize) {
    asm volatile("cp.async.cg.shared.global [%0], [%1], 16, %2;\n" ::
        "r"((unsigned)__cvta_generic_to_shared(dst)), "l"(src), "r"(ssize));
}
__device__ __forceinline__ void cp_commit() {
    asm volatile("cp.async.commit_group;\n" ::: "memory");
}
__device__ __forceinline__ void cp_wait_all() {
    asm volatile("cp.async.wait_group 0;\n" ::: "memory");
}

__device__ __forceinline__ unsigned f2tf32(float x) {
    unsigned r;
    asm("cvt.rna.tf32.f32 %0, %1;" : "=r"(r) : "f"(x));
    return r;
}

// ---------------- degree / norm / CSR build ----------------
__global__ void k_zero_deg() {
    int i = blockIdx.x * blockDim.x + threadIdx.x;
    if (i < N_NODES) { g_deg_in[i] = 0; g_deg_out[i] = 0; }
}

__global__ void k_count(const int* __restrict__ src, const int* __restrict__ dst) {
    int e = blockIdx.x * blockDim.x + threadIdx.x;
    if (e < N_EDGES) {
        atomicAdd(&g_deg_out[src[e]], 1);
        atomicAdd(&g_deg_in [dst[e]], 1);
    }
}

__global__ void k_scan_block() {
    __shared__ int s[1024];
    int i = blockIdx.x * 1024 + threadIdx.x;
    int v = (i < N_NODES) ? g_deg_in[i] : 0;
    s[threadIdx.x] = v;
    __syncthreads();
    for (int off = 1; off < 1024; off <<= 1) {
        int t = (threadIdx.x >= off) ? s[threadIdx.x - off] : 0;
        __syncthreads();
        s[threadIdx.x] += t;
        __syncthreads();
    }
    if (i < N_NODES) g_incl[i] = s[threadIdx.x];
    if (threadIdx.x == 1023) g_blocksum[blockIdx.x] = s[1023];
}

__global__ void k_scan_tot(int nb) {
    __shared__ int s[256];
    int t = threadIdx.x;
    if (t < nb) s[t] = g_blocksum[t];
    __syncthreads();
    if (t == 0) {
        int run = 0;
        for (int b = 0; b < nb; b++) { int tmp = s[b]; s[b] = run; run += tmp; }
    }
    __syncthreads();
    if (t < nb) g_blocksum[t] = s[t];
}

__global__ void k_scan_fin() {
    int i = blockIdx.x * blockDim.x + threadIdx.x;
    if (i < N_NODES) {
        int incl = g_incl[i] + g_blocksum[i >> 10];
        g_incl[i] = incl;
        int di = g_deg_in[i], dout = g_deg_out[i];
        g_cursor[i] = incl - di;
        g_ns[i] = rsqrtf((float)(dout > 1 ? dout : 1));
        g_nd[i] = rsqrtf((float)(di   > 1 ? di   : 1));
    }
}

__global__ void k_fill(const int* __restrict__ src, const int* __restrict__ dst) {
    int e = blockIdx.x * blockDim.x + threadIdx.x;
    if (e < N_EDGES) {
        int pos = atomicAdd(&g_cursor[dst[e]], 1);
        g_csr[pos] = src[e];
    }
}

// ---------------- GEMM1 tf32: h1h = fp16(x @ W1)  (raw, ns applied in agg1) ----------------
__global__ __launch_bounds__(256, 2)
void k_gemm1_tf32(const float* __restrict__ A, const float* __restrict__ W,
                  __half* __restrict__ out, int M) {
    __shared__ float As[2][128][36];
    __shared__ float Bs[2][32][136];

    const int tid  = threadIdx.x;
    const int lane = tid & 31;
    const int w    = tid >> 5;
    const int wm   = w >> 1;
    const int wn   = w & 1;
    const int g    = lane >> 2;
    const int tig  = lane & 3;
    const int rowbase = blockIdx.y * 128;

    float acc[2][8][4];
#pragma unroll
    for (int mi = 0; mi < 2; mi++)
#pragma unroll
        for (int ni = 0; ni < 8; ni++)
#pragma unroll
            for (int j = 0; j < 4; j++) acc[mi][ni][j] = 0.f;

    auto issueA = [&](int k0, int b) {
#pragma unroll
        for (int i = 0; i < 8; i++) {
            int idx = tid + i * 256;
            int m = idx & 127, kq2 = idx >> 7;        // kq2 0..15
            int k = k0 + kq2 * 2;
            int gm = rowbase + m;
            int valid = (gm < M) && (k < NFEAT);
            const float* src = A + (valid ? ((long)gm * NFEAT + k) : 0);
            cp_async8(&As[b][m][kq2 * 2], src, valid ? 8 : 0);
        }
    };
    auto issueB = [&](int k0, int b) {
#pragma unroll
        for (int i = 0; i < 4; i++) {
            int idx = tid + i * 256;
            int n4 = idx & 31, k = idx >> 5;          // k 0..31
            int valid = (k0 + k) < NFEAT;
            const float* src = W + (valid ? ((long)(k0 + k) * 128 + n4 * 4) : 0);
            cp_async16(&Bs[b][k][n4 * 4], src, valid ? 16 : 0);
        }
    };

    const int NIT = (NFEAT + 31) / 32;   // 19

    issueA(0, 0); issueB(0, 0); cp_commit();

    for (int it = 0; it < NIT; it++) {
        const int cur = it & 1;
        cp_wait_all();
        __syncthreads();
        if (it + 1 < NIT) {
            issueA((it + 1) * 32, cur ^ 1);
            issueB((it + 1) * 32, cur ^ 1);
            cp_commit();
        }

#pragma unroll
        for (int kk = 0; kk < 32; kk += 8) {
            unsigned afr[2][4];
#pragma unroll
            for (int mi = 0; mi < 2; mi++) {
                int mb = wm * 32 + mi * 16;
                afr[mi][0] = f2tf32(As[cur][mb + g    ][kk + tig    ]);
                afr[mi][1] = f2tf32(As[cur][mb + g + 8][kk + tig    ]);
                afr[mi][2] = f2tf32(As[cur][mb + g    ][kk + tig + 4]);
                afr[mi][3] = f2tf32(As[cur][mb + g + 8][kk + tig + 4]);
            }
            unsigned bfr[8][2];
#pragma unroll
            for (int ni = 0; ni < 8; ni++) {
                int nb = wn * 64 + ni * 8;
                bfr[ni][0] = f2tf32(Bs[cur][kk + tig    ][nb + g]);
                bfr[ni][1] = f2tf32(Bs[cur][kk + tig + 4][nb + g]);
            }
#pragma unroll
            for (int mi = 0; mi < 2; mi++)
#pragma unroll
                for (int ni = 0; ni < 8; ni++) {
                    asm volatile(
                        "mma.sync.aligned.m16n8k8.row.col.f32.tf32.tf32.f32 "
                        "{%0,%1,%2,%3}, {%4,%5,%6,%7}, {%8,%9}, {%0,%1,%2,%3};"
                        : "+f"(acc[mi][ni][0]), "+f"(acc[mi][ni][1]),
                          "+f"(acc[mi][ni][2]), "+f"(acc[mi][ni][3])
                        : "r"(afr[mi][0]), "r"(afr[mi][1]),
                          "r"(afr[mi][2]), "r"(afr[mi][3]),
                          "r"(bfr[ni][0]), "r"(bfr[ni][1]));
                }
        }
    }

#pragma unroll
    for (int mi = 0; mi < 2; mi++) {
        int row0 = rowbase + wm * 32 + mi * 16 + g;
        int row1 = row0 + 8;
#pragma unroll
        for (int ni = 0; ni < 8; ni++) {
            int col = wn * 64 + ni * 8 + tig * 2;
            if (row0 < M)
                *(__half2*)(out + (long)row0 * HID + col) =
                    __floats2half2_rn(acc[mi][ni][0], acc[mi][ni][1]);
            if (row1 < M)
                *(__half2*)(out + (long)row1 * HID + col) =
                    __floats2half2_rn(acc[mi][ni][2], acc[mi][ni][3]);
        }
    }
}

// ---------------- GEMM2 tf32: h2h = fp16( ns[row] * (h1b @ W2) ) ----------------
__global__ __launch_bounds__(256, 2)
void k_gemm2_tf32(const float* __restrict__ A, const float* __restrict__ W,
                  const float* __restrict__ ns, __half* __restrict__ out, int M) {
    __shared__ float As[2][128][36];
    __shared__ float Bs[2][32][72];

    const int tid  = threadIdx.x;
    const int lane = tid & 31;
    const int w    = tid >> 5;
    const int wm   = w >> 1;
    const int wn   = w & 1;
    const int g    = lane >> 2;
    const int tig  = lane & 3;
    const int rowbase = blockIdx.y * 128;

    float acc[2][4][4];
#pragma unroll
    for (int mi = 0; mi < 2; mi++)
#pragma unroll
        for (int ni = 0; ni < 4; ni++)
#pragma unroll
            for (int j = 0; j < 4; j++) acc[mi][ni][j] = 0.f;

    auto issueA = [&](int k0, int b) {
#pragma unroll
        for (int i = 0; i < 4; i++) {
            int idx = tid + i * 256;                  // 0..1023
            int m = idx >> 3, kq4 = idx & 7;
            int gm = rowbase + m;
            int valid = (gm < M);
            const float* src = A + (valid ? ((long)gm * HID + k0 + kq4 * 4) : 0);
            cp_async16(&As[b][m][kq4 * 4], src, valid ? 16 : 0);
        }
    };
    auto issueB = [&](int k0, int b) {
#pragma unroll
        for (int i = 0; i < 8; i++) {
            int idx = tid + i * 256;                  // 0..2047
            int k = idx >> 6, n = idx & 63;
            int valid = (n < NCLS);
            const float* src = W + (valid ? ((long)(k0 + k) * NCLS + n) : 0);
            cp_async4(&Bs[b][k][n], src, valid ? 4 : 0);
        }
    };

    const int NIT = HID / 32;   // 4

    issueA(0, 0); issueB(0, 0); cp_commit();

    for (int it = 0; it < NIT; it++) {
        const int cur = it & 1;
        cp_wait_all();
        __syncthreads();
        if (it + 1 < NIT) {
            issueA((it + 1) * 32, cur ^ 1);
            issueB((it + 1) * 32, cur ^ 1);
            cp_commit();
        }

#pragma unroll
        for (int kk = 0; kk < 32; kk += 8) {
            unsigned afr[2][4];
#pragma unroll
            for (int mi = 0; mi < 2; mi++) {
                int mb = wm * 32 + mi * 16;
                afr[mi][0] = f2tf32(As[cur][mb + g    ][kk + tig    ]);
                afr[mi][1] = f2tf32(As[cur][mb + g + 8][kk + tig    ]);
                afr[mi][2] = f2tf32(As[cur][mb + g    ][kk + tig + 4]);
                afr[mi][3] = f2tf32(As[cur][mb + g + 8][kk + tig + 4]);
            }
            unsigned bfr[4][2];
#pragma unroll
            for (int ni = 0; ni < 4; ni++) {
                int nb = wn * 32 + ni * 8;
                bfr[ni][0] = f2tf32(Bs[cur][kk + tig    ][nb + g]);
                bfr[ni][1] = f2tf32(Bs[cur][kk + tig + 4][nb + g]);
            }
#pragma unroll
            for (int mi = 0; mi < 2; mi++)
#pragma unroll
                for (int ni = 0; ni < 4; ni++) {
                    asm volatile(
                        "mma.sync.aligned.m16n8k8.row.col.f32.tf32.tf32.f32 "
                        "{%0,%1,%2,%3}, {%4,%5,%6,%7}, {%8,%9}, {%0,%1,%2,%3};"
                        : "+f"(acc[mi][ni][0]), "+f"(acc[mi][ni][1]),
                          "+f"(acc[mi][ni][2]), "+f"(acc[mi][ni][3])
                        : "r"(afr[mi][0]), "r"(afr[mi][1]),
                          "r"(afr[mi][2]), "r"(afr[mi][3]),
                          "r"(bfr[ni][0]), "r"(bfr[ni][1]));
                }
        }
    }

#pragma unroll
    for (int mi = 0; mi < 2; mi++) {
        int row0 = rowbase + wm * 32 + mi * 16 + g;
        int row1 = row0 + 8;
        float s0 = (row0 < M) ? ns[row0] : 0.f;
        float s1 = (row1 < M) ? ns[row1] : 0.f;
#pragma unroll
        for (int ni = 0; ni < 4; ni++) {
            int col = wn * 32 + ni * 8 + tig * 2;
            if (col <= 40) {                          // col 40 pair also writes pad col 41 (acc=0)
                if (row0 < M)
                    *(__half2*)(out + (long)row0 * H2S + col) =
                        __floats2half2_rn(acc[mi][ni][0] * s0, acc[mi][ni][1] * s0);
                if (row1 < M)
                    *(__half2*)(out + (long)row1 * H2S + col) =
                        __floats2half2_rn(acc[mi][ni][2] * s1, acc[mi][ni][3] * s1);
            }
        }
    }
}

// ---------------- layer-1 aggregation: warp/node fp16 gather, ns[src] fused ----------------
__global__ void k_agg1(const float* __restrict__ b1) {
    int node = (blockIdx.x * blockDim.x + threadIdx.x) >> 5;
    int lane = threadIdx.x & 31;
    if (node >= N_NODES) return;
    int end = g_incl[node];
    int j = end - g_deg_in[node];
    float a0 = 0.f, a1 = 0.f, a2 = 0.f, a3 = 0.f;

    auto body = [&](int s) {
        float nsv = g_ns[s];
        uint2 u = *((const uint2*)(g_h1h + (size_t)s * HID) + lane);
        float2 f0 = __half22float2(*(const __half2*)&u.x);
        float2 f1 = __half22float2(*(const __half2*)&u.y);
        a0 = fmaf(nsv, f0.x, a0);
        a1 = fmaf(nsv, f0.y, a1);
        a2 = fmaf(nsv, f1.x, a2);
        a3 = fmaf(nsv, f1.y, a3);
    };

    for (; j + 4 <= end; j += 4) {
        int s0 = g_csr[j], s1 = g_csr[j + 1], s2 = g_csr[j + 2], s3 = g_csr[j + 3];
        body(s0); body(s1); body(s2); body(s3);
    }
    for (; j < end; j++) body(g_csr[j]);

    float nd = g_nd[node];
    float4 bb = ((const float4*)b1)[lane];
    float4 o;
    o.x = fmaxf(a0 * nd + bb.x, 0.f);
    o.y = fmaxf(a1 * nd + bb.y, 0.f);
    o.z = fmaxf(a2 * nd + bb.z, 0.f);
    o.w = fmaxf(a3 * nd + bb.w, 0.f);
    *((float4*)(g_h1b + (long)node * HID) + lane) = o;
}

// ---------------- layer-2 aggregation: warp/node fp16 gather, fuse nd+bias ----------------
__global__ void k_agg2(const float* __restrict__ b2, float* __restrict__ out) {
    int node = (blockIdx.x * blockDim.x + threadIdx.x) >> 5;
    int lane = threadIdx.x & 31;
    if (node >= N_NODES) return;
    int end = g_incl[node];
    int j = end - g_deg_in[node];
    int c = lane * 2;                  // cols c, c+1 ; lanes 0..20 active
    bool act = (c < NCLS + 1);         // c <= 40
    float a0 = 0.f, a1 = 0.f;

    for (; j + 4 <= end; j += 4) {
        int s0 = g_csr[j], s1 = g_csr[j + 1], s2 = g_csr[j + 2], s3 = g_csr[j + 3];
        if (act) {
            float2 f0 = __half22float2(*(const __half2*)(g_h2h + (size_t)s0 * H2S + c));
            float2 f1 = __half22float2(*(const __half2*)(g_h2h + (size_t)s1 * H2S + c));
            float2 f2 = __half22float2(*(const __half2*)(g_h2h + (size_t)s2 * H2S + c));
            float2 f3 = __half22float2(*(const __half2*)(g_h2h + (size_t)s3 * H2S + c));
            a0 += f0.x + f1.x + f2.x + f3.x;
            a1 += f0.y + f1.y + f2.y + f3.y;
        }
    }
    for (; j < end; j++) {
        int s = g_csr[j];
        if (act) {
            float2 f = __half22float2(*(const __half2*)(g_h2h + (size_t)s * H2S + c));
            a0 += f.x; a1 += f.y;
        }
    }
    if (act) {
        float nd = g_nd[node];
        float* po = out + (long)node * NCLS;
        po[c] = a0 * nd + b2[c];
        if (c + 1 < NCLS) po[c + 1] = a1 * nd + b2[c + 1];
    }
}

// ---------------- launcher ----------------
extern "C" void kernel_launch(void* const* d_in, const int* in_sizes, int n_in,
                              void* d_out, int out_size) {
    const float* x    = (const float*)d_in[0];
    const int*   esrc = (const int*)  d_in[1];
    const int*   edst = (const int*)  d_in[2];
    const float* W1   = (const float*)d_in[3];
    const float* b1   = (const float*)d_in[4];
    const float* W2   = (const float*)d_in[5];
    const float* b2   = (const float*)d_in[6];
    float*       out  = (float*)d_out;

    __half *p_h1h, *p_h2h;
    float  *p_h1b, *p_ns;
    cudaGetSymbolAddress((void**)&p_h1h, g_h1h);
    cudaGetSymbolAddress((void**)&p_h1b, g_h1b);
    cudaGetSymbolAddress((void**)&p_h2h, g_h2h);
    cudaGetSymbolAddress((void**)&p_ns,  g_ns);

    const int TB = 256;

    // fork: GEMM1 (independent of edges) on s2, CSR chain on default stream
    cudaEventRecord(g_ev_fork, 0);
    cudaStreamWaitEvent(g_s2, g_ev_fork, 0);
    {
        dim3 grid(1, (N_NODES + 127) / 128);
        k_gemm1_tf32<<<grid, 256, 0, g_s2>>>(x, W1, p_h1h, N_NODES);
    }
    cudaEventRecord(g_ev_join, g_s2);

    // CSR + norms on default stream
    k_zero_deg<<<(N_NODES + TB - 1) / TB, TB>>>();
    k_count   <<<(N_EDGES + TB - 1) / TB, TB>>>(esrc, edst);
    int nb = (N_NODES + 1023) / 1024;
    k_scan_block<<<nb, 1024>>>();
    k_scan_tot  <<<1, 256>>>(nb);
    k_scan_fin  <<<(N_NODES + TB - 1) / TB, TB>>>();
    k_fill      <<<(N_EDGES + TB - 1) / TB, TB>>>(esrc, edst);

    // join: agg1 needs h1h + csr + ns + nd
    cudaStreamWaitEvent(0, g_ev_join, 0);
    k_agg1<<<(N_NODES * 32 + TB - 1) / TB, TB>>>(b1);

    // layer 2
    {
        dim3 grid(1, (N_NODES + 127) / 128);
        k_gemm2_tf32<<<grid, 256>>>(p_h1b, W2, p_ns, p_h2h, N_NODES);
    }
    k_agg2<<<(N_NODES * 32 + TB - 1) / TB, TB>>>(b2, out);
}

// round 7
// speedup vs baseline: 6.1604x; 1.0900x over previous
#include <cuda_runtime.h>
#include <cuda_fp16.h>
#include <cuda_bf16.h>

#define N_NODES  100000
#define N_EDGES  1600000
#define NFEAT    602
#define NFEATP   608     // padded to 19*32
#define HID      128
#define NCLS     41
#define H2S      48      // padded h2 row stride in halves (cols 41..47 pad)

// ---------------- device scratch (no allocations allowed) ----------------
__device__ int   g_deg_in[N_NODES];
__device__ int   g_deg_out[N_NODES];
__device__ float g_ns[N_NODES];          // deg_out^-1/2 (clipped)
__device__ float g_nd[N_NODES];          // deg_in^-1/2  (clipped)
__device__ int   g_incl[N_NODES];        // inclusive prefix sum of deg_in
__device__ int   g_blocksum[256];
__device__ int   g_cursor[N_NODES];
__device__ int   g_csr[N_EDGES];         // src ids grouped by dst
__device__ __align__(16) __half g_h1h [(size_t)N_NODES * HID];  // raw x@W1 (no ns), fp16
__device__ __align__(16) __half g_h1bh[(size_t)N_NODES * HID];  // relu'd layer-1 out, fp16
__device__ __align__(16) __half g_h2h [(size_t)N_NODES * H2S];  // ns*(h1b@W2), fp16
__device__ __align__(16) __half g_w1ht[128][NFEATP];            // W1^T fp16, zero-padded
__device__ __align__(16) __half g_w2ht[64][HID];                // W2^T fp16, zero-padded

// ---------------- streams/events for fork-join (created before harness baseline) ----
static cudaStream_t g_s2;
static cudaEvent_t  g_ev_fork, g_ev_join;
namespace {
struct StreamInit {
    StreamInit() {
        cudaStreamCreateWithFlags(&g_s2, cudaStreamNonBlocking);
        cudaEventCreateWithFlags(&g_ev_fork, cudaEventDisableTiming);
        cudaEventCreateWithFlags(&g_ev_join, cudaEventDisableTiming);
    }
};
StreamInit g_stream_init;
}

// ---------------- cp.async helpers ----------------
__device__ __forceinline__ void cp_async8(void* dst, const void* src, int ssize) {
    asm volatile("cp.async.ca.shared.global [%0], [%1], 8, %2;\n" ::
        "r"((unsigned)__cvta_generic_to_shared(dst)), "l"(src), "r"(ssize));
}
__device__ __forceinline__ void cp_async16(void* dst, const void* src, int ssize) {
    asm volatile("cp.async.cg.shared.global [%0], [%1], 16, %2;\n" ::
        "r"((unsigned)__cvta_generic_to_shared(dst)), "l"(src), "r"(ssize));
}
__device__ __forceinline__ void cp_commit() {
    asm volatile("cp.async.commit_group;\n" ::: "memory");
}
__device__ __forceinline__ void cp_wait_all() {
    asm volatile("cp.async.wait_group 0;\n" ::: "memory");
}

__device__ __forceinline__ unsigned packh2(float lo, float hi) {
    __half2 h = __floats2half2_rn(lo, hi);
    return *(unsigned*)&h;
}

// ---------------- degree / norm / CSR build ----------------
__global__ void k_zero_deg() {
    int i = blockIdx.x * blockDim.x + threadIdx.x;
    if (i < N_NODES) { g_deg_in[i] = 0; g_deg_out[i] = 0; }
}

__global__ void k_count(const int* __restrict__ src, const int* __restrict__ dst) {
    int e = blockIdx.x * blockDim.x + threadIdx.x;
    if (e < N_EDGES) {
        atomicAdd(&g_deg_out[src[e]], 1);
        atomicAdd(&g_deg_in [dst[e]], 1);
    }
}

__global__ void k_scan_block() {
    __shared__ int s[1024];
    int i = blockIdx.x * 1024 + threadIdx.x;
    int v = (i < N_NODES) ? g_deg_in[i] : 0;
    s[threadIdx.x] = v;
    __syncthreads();
    for (int off = 1; off < 1024; off <<= 1) {
        int t = (threadIdx.x >= off) ? s[threadIdx.x - off] : 0;
        __syncthreads();
        s[threadIdx.x] += t;
        __syncthreads();
    }
    if (i < N_NODES) g_incl[i] = s[threadIdx.x];
    if (threadIdx.x == 1023) g_blocksum[blockIdx.x] = s[1023];
}

__global__ void k_scan_tot(int nb) {
    __shared__ int s[256];
    int t = threadIdx.x;
    if (t < nb) s[t] = g_blocksum[t];
    __syncthreads();
    if (t == 0) {
        int run = 0;
        for (int b = 0; b < nb; b++) { int tmp = s[b]; s[b] = run; run += tmp; }
    }
    __syncthreads();
    if (t < nb) g_blocksum[t] = s[t];
}

__global__ void k_scan_fin() {
    int i = blockIdx.x * blockDim.x + threadIdx.x;
    if (i < N_NODES) {
        int incl = g_incl[i] + g_blocksum[i >> 10];
        g_incl[i] = incl;
        int di = g_deg_in[i], dout = g_deg_out[i];
        g_cursor[i] = incl - di;
        g_ns[i] = rsqrtf((float)(dout > 1 ? dout : 1));
        g_nd[i] = rsqrtf((float)(di   > 1 ? di   : 1));
    }
}

__global__ void k_fill(const int* __restrict__ src, const int* __restrict__ dst) {
    int e = blockIdx.x * blockDim.x + threadIdx.x;
    if (e < N_EDGES) {
        int pos = atomicAdd(&g_cursor[dst[e]], 1);
        g_csr[pos] = src[e];
    }
}

// ---------------- weight convert: W1 [602][128] -> g_w1ht [128][608] fp16 (transposed),
//                  W2 [128][41] -> g_w2ht [64][128] fp16 (transposed) ----------------
__global__ void k_cvtW(const float* __restrict__ W1, const float* __restrict__ W2) {
    int i = blockIdx.x * blockDim.x + threadIdx.x;
    int tot1 = 128 * NFEATP;
    if (i < tot1) {
        int n = i / NFEATP, k = i % NFEATP;
        float v = (k < NFEAT) ? W1[(long)k * HID + n] : 0.f;
        g_w1ht[n][k] = __float2half_rn(v);
    } else {
        int j = i - tot1;                 // 64*128 entries
        if (j < 64 * HID) {
            int n = j / HID, k = j % HID;
            float v = (n < NCLS) ? W2[(long)k * NCLS + n] : 0.f;
            g_w2ht[n][k] = __float2half_rn(v);
        }
    }
}

// ---------------- GEMM1 fp16 HMMA: h1h = fp16(x @ W1)  (raw; ns applied in agg1) -----
// BM=128 BN=128 BK=32, 256 thr, 8 warps (wm 0..3 x wn 0..1), warp tile 32x64, m16n8k16.
__global__ __launch_bounds__(256, 2)
void k_gemm1_f16(const float* __restrict__ A, __half* __restrict__ out, int M) {
    __shared__ float  As[2][128][36];     // fp32 x tile
    __shared__ __half Bs[2][128][40];     // W1^T tile [n][k], stride 40 halves

    const int tid  = threadIdx.x;
    const int lane = tid & 31;
    const int w    = tid >> 5;
    const int wm   = w >> 1;
    const int wn   = w & 1;
    const int g    = lane >> 2;
    const int tig  = lane & 3;
    const int rowbase = blockIdx.y * 128;

    float acc[2][8][4];
#pragma unroll
    for (int mi = 0; mi < 2; mi++)
#pragma unroll
        for (int ni = 0; ni < 8; ni++)
#pragma unroll
            for (int j = 0; j < 4; j++) acc[mi][ni][j] = 0.f;

    auto issueA = [&](int k0, int b) {
#pragma unroll
        for (int i = 0; i < 8; i++) {
            int idx = tid + i * 256;
            int m = idx & 127, kq2 = idx >> 7;        // kq2 0..15
            int k = k0 + kq2 * 2;
            int gm = rowbase + m;
            int valid = (gm < M) && (k < NFEAT);
            const float* src = A + (valid ? ((long)gm * NFEAT + k) : 0);
            cp_async8(&As[b][m][kq2 * 2], src, valid ? 8 : 0);
        }
    };
    auto issueB = [&](int k0, int b) {
        // 128 n-rows x 32 halves (64B) = 512 x 16B chunks, 2 per thread
#pragma unroll
        for (int i = 0; i < 2; i++) {
            int idx = tid + i * 256;
            int n = idx >> 2, c = idx & 3;            // c: 8-half chunk
            cp_async16(&Bs[b][n][c * 8], &g_w1ht[n][k0 + c * 8], 16);
        }
    };

    const int NIT = NFEATP / 32;   // 19

    issueA(0, 0); issueB(0, 0); cp_commit();

    for (int it = 0; it < NIT; it++) {
        const int cur = it & 1;
        cp_wait_all();
        __syncthreads();
        if (it + 1 < NIT) {
            issueA((it + 1) * 32, cur ^ 1);
            issueB((it + 1) * 32, cur ^ 1);
            cp_commit();
        }

#pragma unroll
        for (int kk = 0; kk < 32; kk += 16) {
            unsigned afr[2][4];
#pragma unroll
            for (int mi = 0; mi < 2; mi++) {
                int mb = wm * 32 + mi * 16;
                float2 v0 = *(const float2*)&As[cur][mb + g    ][kk + tig * 2];
                float2 v1 = *(const float2*)&As[cur][mb + g + 8][kk + tig * 2];
                float2 v2 = *(const float2*)&As[cur][mb + g    ][kk + tig * 2 + 8];
                float2 v3 = *(const float2*)&As[cur][mb + g + 8][kk + tig * 2 + 8];
                afr[mi][0] = packh2(v0.x, v0.y);
                afr[mi][1] = packh2(v1.x, v1.y);
                afr[mi][2] = packh2(v2.x, v2.y);
                afr[mi][3] = packh2(v3.x, v3.y);
            }
            unsigned bfr[8][2];
#pragma unroll
            for (int ni = 0; ni < 8; ni++) {
                int nb = wn * 64 + ni * 8 + g;
                bfr[ni][0] = *(const unsigned*)&Bs[cur][nb][kk + tig * 2];
                bfr[ni][1] = *(const unsigned*)&Bs[cur][nb][kk + tig * 2 + 8];
            }
#pragma unroll
            for (int mi = 0; mi < 2; mi++)
#pragma unroll
                for (int ni = 0; ni < 8; ni++) {
                    asm volatile(
                        "mma.sync.aligned.m16n8k16.row.col.f32.f16.f16.f32 "
                        "{%0,%1,%2,%3}, {%4,%5,%6,%7}, {%8,%9}, {%0,%1,%2,%3};"
                        : "+f"(acc[mi][ni][0]), "+f"(acc[mi][ni][1]),
                          "+f"(acc[mi][ni][2]), "+f"(acc[mi][ni][3])
                        : "r"(afr[mi][0]), "r"(afr[mi][1]),
                          "r"(afr[mi][2]), "r"(afr[mi][3]),
                          "r"(bfr[ni][0]), "r"(bfr[ni][1]));
                }
        }
    }

#pragma unroll
    for (int mi = 0; mi < 2; mi++) {
        int row0 = rowbase + wm * 32 + mi * 16 + g;
        int row1 = row0 + 8;
#pragma unroll
        for (int ni = 0; ni < 8; ni++) {
            int col = wn * 64 + ni * 8 + tig * 2;
            if (row0 < M)
                *(__half2*)(out + (long)row0 * HID + col) =
                    __floats2half2_rn(acc[mi][ni][0], acc[mi][ni][1]);
            if (row1 < M)
                *(__half2*)(out + (long)row1 * HID + col) =
                    __floats2half2_rn(acc[mi][ni][2], acc[mi][ni][3]);
        }
    }
}

// ---------------- GEMM2 fp16 HMMA: h2h = fp16( ns[row] * (h1bh @ W2) ) ----------------
// BM=128 BN=64 BK=32, 256 thr, warp tile 32x32.
__global__ __launch_bounds__(256, 2)
void k_gemm2_f16(const float* __restrict__ ns, __half* __restrict__ out, int M) {
    __shared__ __half As[2][128][40];     // h1bh tile [m][k], stride 40 halves
    __shared__ __half Bs[2][64][40];      // W2^T tile [n][k]

    const int tid  = threadIdx.x;
    const int lane = tid & 31;
    const int w    = tid >> 5;
    const int wm   = w >> 1;
    const int wn   = w & 1;
    const int g    = lane >> 2;
    const int tig  = lane & 3;
    const int rowbase = blockIdx.y * 128;

    float acc[2][4][4];
#pragma unroll
    for (int mi = 0; mi < 2; mi++)
#pragma unroll
        for (int ni = 0; ni < 4; ni++)
#pragma unroll
            for (int j = 0; j < 4; j++) acc[mi][ni][j] = 0.f;

    auto issueA = [&](int k0, int b) {
        // 128 rows x 32 halves = 512 x 16B chunks, 2 per thread
#pragma unroll
        for (int i = 0; i < 2; i++) {
            int idx = tid + i * 256;
            int m = idx >> 2, c = idx & 3;
            int gm = rowbase + m;
            int valid = (gm < M);
            const __half* src = g_h1bh + (valid ? ((size_t)gm * HID + k0 + c * 8) : 0);
            cp_async16(&As[b][m][c * 8], src, valid ? 16 : 0);
        }
    };
    auto issueB = [&](int k0, int b) {
        // 64 n-rows x 32 halves = 256 x 16B chunks, 1 per thread
        int n = tid >> 2, c = tid & 3;
        cp_async16(&Bs[b][n][c * 8], &g_w2ht[n][k0 + c * 8], 16);
    };

    const int NIT = HID / 32;   // 4

    issueA(0, 0); issueB(0, 0); cp_commit();

    for (int it = 0; it < NIT; it++) {
        const int cur = it & 1;
        cp_wait_all();
        __syncthreads();
        if (it + 1 < NIT) {
            issueA((it + 1) * 32, cur ^ 1);
            issueB((it + 1) * 32, cur ^ 1);
            cp_commit();
        }

#pragma unroll
        for (int kk = 0; kk < 32; kk += 16) {
            unsigned afr[2][4];
#pragma unroll
            for (int mi = 0; mi < 2; mi++) {
                int mb = wm * 32 + mi * 16;
                afr[mi][0] = *(const unsigned*)&As[cur][mb + g    ][kk + tig * 2];
                afr[mi][1] = *(const unsigned*)&As[cur][mb + g + 8][kk + tig * 2];
                afr[mi][2] = *(const unsigned*)&As[cur][mb + g    ][kk + tig * 2 + 8];
                afr[mi][3] = *(const unsigned*)&As[cur][mb + g + 8][kk + tig * 2 + 8];
            }
            unsigned bfr[4][2];
#pragma unroll
            for (int ni = 0; ni < 4; ni++) {
                int nb = wn * 32 + ni * 8 + g;
                bfr[ni][0] = *(const unsigned*)&Bs[cur][nb][kk + tig * 2];
                bfr[ni][1] = *(const unsigned*)&Bs[cur][nb][kk + tig * 2 + 8];
            }
#pragma unroll
            for (int mi = 0; mi < 2; mi++)
#pragma unroll
                for (int ni = 0; ni < 4; ni++) {
                    asm volatile(
                        "mma.sync.aligned.m16n8k16.row.col.f32.f16.f16.f32 "
                        "{%0,%1,%2,%3}, {%4,%5,%6,%7}, {%8,%9}, {%0,%1,%2,%3};"
                        : "+f"(acc[mi][ni][0]), "+f"(acc[mi][ni][1]),
                          "+f"(acc[mi][ni][2]), "+f"(acc[mi][ni][3])
                        : "r"(afr[mi][0]), "r"(afr[mi][1]),
                          "r"(afr[mi][2]), "r"(afr[mi][3]),
                          "r"(bfr[ni][0]), "r"(bfr[ni][1]));
                }
        }
    }

#pragma unroll
    for (int mi = 0; mi < 2; mi++) {
        int row0 = rowbase + wm * 32 + mi * 16 + g;
        int row1 = row0 + 8;
        float s0 = (row0 < M) ? ns[row0] : 0.f;
        float s1 = (row1 < M) ? ns[row1] : 0.f;
#pragma unroll
        for (int ni = 0; ni < 4; ni++) {
            int col = wn * 32 + ni * 8 + tig * 2;
            if (col <= 40) {                          // col 40 pair also writes pad col 41
                if (row0 < M)
                    *(__half2*)(out + (long)row0 * H2S + col) =
                        __floats2half2_rn(acc[mi][ni][0] * s0, acc[mi][ni][1] * s0);
                if (row1 < M)
                    *(__half2*)(out + (long)row1 * H2S + col) =
                        __floats2half2_rn(acc[mi][ni][2] * s1, acc[mi][ni][3] * s1);
            }
        }
    }
}

// ---------------- layer-1 aggregation: warp/node fp16 gather, ns[src] fused, fp16 out --
__global__ void k_agg1(const float* __restrict__ b1) {
    int node = (blockIdx.x * blockDim.x + threadIdx.x) >> 5;
    int lane = threadIdx.x & 31;
    if (node >= N_NODES) return;
    int end = g_incl[node];
    int j = end - g_deg_in[node];
    float a0 = 0.f, a1 = 0.f, a2 = 0.f, a3 = 0.f;

    auto body = [&](int s) {
        float nsv = g_ns[s];
        uint2 u = *((const uint2*)(g_h1h + (size_t)s * HID) + lane);
        float2 f0 = __half22float2(*(const __half2*)&u.x);
        float2 f1 = __half22float2(*(const __half2*)&u.y);
        a0 = fmaf(nsv, f0.x, a0);
        a1 = fmaf(nsv, f0.y, a1);
        a2 = fmaf(nsv, f1.x, a2);
        a3 = fmaf(nsv, f1.y, a3);
    };

    for (; j + 4 <= end; j += 4) {
        int s0 = g_csr[j], s1 = g_csr[j + 1], s2 = g_csr[j + 2], s3 = g_csr[j + 3];
        body(s0); body(s1); body(s2); body(s3);
    }
    for (; j < end; j++) body(g_csr[j]);

    float nd = g_nd[node];
    float4 bb = ((const float4*)b1)[lane];
    uint2 o;
    o.x = packh2(fmaxf(a0 * nd + bb.x, 0.f), fmaxf(a1 * nd + bb.y, 0.f));
    o.y = packh2(fmaxf(a2 * nd + bb.z, 0.f), fmaxf(a3 * nd + bb.w, 0.f));
    *((uint2*)(g_h1bh + (size_t)node * HID) + lane) = o;
}

// ---------------- layer-2 aggregation: warp/node fp16 gather, fuse nd+bias ----------------
__global__ void k_agg2(const float* __restrict__ b2, float* __restrict__ out) {
    int node = (blockIdx.x * blockDim.x + threadIdx.x) >> 5;
    int lane = threadIdx.x & 31;
    if (node >= N_NODES) return;
    int end = g_incl[node];
    int j = end - g_deg_in[node];
    int c = lane * 2;                  // cols c, c+1 ; lanes 0..20 active
    bool act = (c < NCLS + 1);         // c <= 40
    float a0 = 0.f, a1 = 0.f;

    for (; j + 4 <= end; j += 4) {
        int s0 = g_csr[j], s1 = g_csr[j + 1], s2 = g_csr[j + 2], s3 = g_csr[j + 3];
        if (act) {
            float2 f0 = __half22float2(*(const __half2*)(g_h2h + (size_t)s0 * H2S + c));
            float2 f1 = __half22float2(*(const __half2*)(g_h2h + (size_t)s1 * H2S + c));
            float2 f2 = __half22float2(*(const __half2*)(g_h2h + (size_t)s2 * H2S + c));
            float2 f3 = __half22float2(*(const __half2*)(g_h2h + (size_t)s3 * H2S + c));
            a0 += f0.x + f1.x + f2.x + f3.x;
            a1 += f0.y + f1.y + f2.y + f3.y;
        }
    }
    for (; j < end; j++) {
        int s = g_csr[j];
        if (act) {
            float2 f = __half22float2(*(const __half2*)(g_h2h + (size_t)s * H2S + c));
            a0 += f.x; a1 += f.y;
        }
    }
    if (act) {
        float nd = g_nd[node];
        float* po = out + (long)node * NCLS;
        po[c] = a0 * nd + b2[c];
        if (c + 1 < NCLS) po[c + 1] = a1 * nd + b2[c + 1];
    }
}

// ---------------- launcher ----------------
extern "C" void kernel_launch(void* const* d_in, const int* in_sizes, int n_in,
                              void* d_out, int out_size) {
    const float* x    = (const float*)d_in[0];
    const int*   esrc = (const int*)  d_in[1];
    const int*   edst = (const int*)  d_in[2];
    const float* W1   = (const float*)d_in[3];
    const float* b1   = (const float*)d_in[4];
    const float* W2   = (const float*)d_in[5];
    const float* b2   = (const float*)d_in[6];
    float*       out  = (float*)d_out;

    __half *p_h1h, *p_h2h;
    float  *p_ns;
    cudaGetSymbolAddress((void**)&p_h1h, g_h1h);
    cudaGetSymbolAddress((void**)&p_h2h, g_h2h);
    cudaGetSymbolAddress((void**)&p_ns,  g_ns);

    const int TB = 256;

    // fork: weight-convert + GEMM1 (independent of edges) on s2; CSR chain on stream 0
    cudaEventRecord(g_ev_fork, 0);
    cudaStreamWaitEvent(g_s2, g_ev_fork, 0);
    {
        int tot = 128 * NFEATP + 64 * HID;
        k_cvtW<<<(tot + TB - 1) / TB, TB, 0, g_s2>>>(W1, W2);
        dim3 grid(1, (N_NODES + 127) / 128);
        k_gemm1_f16<<<grid, 256, 0, g_s2>>>(x, p_h1h, N_NODES);
    }
    cudaEventRecord(g_ev_join, g_s2);

    // CSR + norms on default stream
    k_zero_deg<<<(N_NODES + TB - 1) / TB, TB>>>();
    k_count   <<<(N_EDGES + TB - 1) / TB, TB>>>(esrc, edst);
    int nb = (N_NODES + 1023) / 1024;
    k_scan_block<<<nb, 1024>>>();
    k_scan_tot  <<<1, 256>>>(nb);
    k_scan_fin  <<<(N_NODES + TB - 1) / TB, TB>>>();
    k_fill      <<<(N_EDGES + TB - 1) / TB, TB>>>(esrc, edst);

    // join: agg1 needs h1h + csr + ns + nd
    cudaStreamWaitEvent(0, g_ev_join, 0);
    k_agg1<<<(N_NODES * 32 + TB - 1) / TB, TB>>>(b1);

    // layer 2 (all fp16 tensor path)
    {
        dim3 grid(1, (N_NODES + 127) / 128);
        k_gemm2_f16<<<grid, 256>>>(p_ns, p_h2h, N_NODES);
    }
    k_agg2<<<(N_NODES * 32 + TB - 1) / TB, TB>>>(b2, out);
}

// round 8
// speedup vs baseline: 7.3448x; 1.1922x over previous
#include <cuda_runtime.h>
#include <cuda_fp16.h>
#include <cuda_bf16.h>

#define N_NODES  100000
#define N_EDGES  1600000
#define NFEAT    602
#define NFEATP   608     // padded to 19*32
#define HID      128
#define NCLS     41
#define H2S      48      // padded h2 row stride in halves (cols 41..47 pad)

// ---------------- device scratch (no allocations allowed) ----------------
__device__ int   g_deg_in[N_NODES];
__device__ int   g_deg_out[N_NODES];
__device__ float g_ns[N_NODES];          // deg_out^-1/2 (clipped)
__device__ float g_nd[N_NODES];          // deg_in^-1/2  (clipped)
__device__ int   g_incl[N_NODES];        // inclusive prefix sum of deg_in
__device__ int   g_blocksum[256];
__device__ int   g_cursor[N_NODES];
__device__ int   g_csr[N_EDGES];         // src ids grouped by dst
__device__ __align__(16) __half g_h1h [(size_t)N_NODES * HID];  // raw x@W1 (no ns), fp16
__device__ __align__(16) __half g_h1bh[(size_t)N_NODES * HID];  // relu'd layer-1 out, fp16
__device__ __align__(16) __half g_h2h [(size_t)N_NODES * H2S];  // ns*(h1b@W2), fp16
__device__ __align__(16) __half g_w1ht[128][NFEATP];            // W1^T fp16, zero-padded
__device__ __align__(16) __half g_w2ht[64][HID];                // W2^T fp16, zero-padded

// ---------------- streams/events for fork-join (created before harness baseline) ----
static cudaStream_t g_s2;
static cudaEvent_t  g_ev_fork, g_ev_join;
namespace {
struct StreamInit {
    StreamInit() {
        cudaStreamCreateWithFlags(&g_s2, cudaStreamNonBlocking);
        cudaEventCreateWithFlags(&g_ev_fork, cudaEventDisableTiming);
        cudaEventCreateWithFlags(&g_ev_join, cudaEventDisableTiming);
    }
};
StreamInit g_stream_init;
}

// ---------------- cp.async helpers ----------------
__device__ __forceinline__ void cp_async8(void* dst, const void* src, int ssize) {
    asm volatile("cp.async.ca.shared.global [%0], [%1], 8, %2;\n" ::
        "r"((unsigned)__cvta_generic_to_shared(dst)), "l"(src), "r"(ssize));
}
__device__ __forceinline__ void cp_async16(void* dst, const void* src, int ssize) {
    asm volatile("cp.async.cg.shared.global [%0], [%1], 16, %2;\n" ::
        "r"((unsigned)__cvta_generic_to_shared(dst)), "l"(src), "r"(ssize));
}
__device__ __forceinline__ void cp_commit() {
    asm volatile("cp.async.commit_group;\n" ::: "memory");
}
__device__ __forceinline__ void cp_wait_all() {
    asm volatile("cp.async.wait_group 0;\n" ::: "memory");
}
__device__ __forceinline__ void cp_wait_1() {
    asm volatile("cp.async.wait_group 1;\n" ::: "memory");
}

__device__ __forceinline__ unsigned packh2(float lo, float hi) {
    __half2 h = __floats2half2_rn(lo, hi);
    return *(unsigned*)&h;
}

// ---------------- degree / norm / CSR build ----------------
__global__ void k_zero_deg() {
    int i = blockIdx.x * blockDim.x + threadIdx.x;
    if (i < N_NODES) { g_deg_in[i] = 0; g_deg_out[i] = 0; }
}

__global__ void k_count(const int* __restrict__ src, const int* __restrict__ dst) {
    int e = blockIdx.x * blockDim.x + threadIdx.x;
    if (e < N_EDGES) {
        atomicAdd(&g_deg_out[src[e]], 1);
        atomicAdd(&g_deg_in [dst[e]], 1);
    }
}

__global__ void k_scan_block() {
    __shared__ int s[1024];
    int i = blockIdx.x * 1024 + threadIdx.x;
    int v = (i < N_NODES) ? g_deg_in[i] : 0;
    s[threadIdx.x] = v;
    __syncthreads();
    for (int off = 1; off < 1024; off <<= 1) {
        int t = (threadIdx.x >= off) ? s[threadIdx.x - off] : 0;
        __syncthreads();
        s[threadIdx.x] += t;
        __syncthreads();
    }
    if (i < N_NODES) g_incl[i] = s[threadIdx.x];
    if (threadIdx.x == 1023) g_blocksum[blockIdx.x] = s[1023];
}

__global__ void k_scan_tot(int nb) {
    __shared__ int s[256];
    int t = threadIdx.x;
    if (t < nb) s[t] = g_blocksum[t];
    __syncthreads();
    if (t == 0) {
        int run = 0;
        for (int b = 0; b < nb; b++) { int tmp = s[b]; s[b] = run; run += tmp; }
    }
    __syncthreads();
    if (t < nb) g_blocksum[t] = s[t];
}

__global__ void k_scan_fin() {
    int i = blockIdx.x * blockDim.x + threadIdx.x;
    if (i < N_NODES) {
        int incl = g_incl[i] + g_blocksum[i >> 10];
        g_incl[i] = incl;
        int di = g_deg_in[i], dout = g_deg_out[i];
        g_cursor[i] = incl - di;
        g_ns[i] = rsqrtf((float)(dout > 1 ? dout : 1));
        g_nd[i] = rsqrtf((float)(di   > 1 ? di   : 1));
    }
}

__global__ void k_fill(const int* __restrict__ src, const int* __restrict__ dst) {
    int e = blockIdx.x * blockDim.x + threadIdx.x;
    if (e < N_EDGES) {
        int pos = atomicAdd(&g_cursor[dst[e]], 1);
        g_csr[pos] = src[e];
    }
}

// ---------------- weight convert ----------------
__global__ void k_cvtW(const float* __restrict__ W1, const float* __restrict__ W2) {
    int i = blockIdx.x * blockDim.x + threadIdx.x;
    int tot1 = 128 * NFEATP;
    if (i < tot1) {
        int n = i / NFEATP, k = i % NFEATP;
        float v = (k < NFEAT) ? W1[(long)k * HID + n] : 0.f;
        g_w1ht[n][k] = __float2half_rn(v);
    } else {
        int j = i - tot1;
        if (j < 64 * HID) {
            int n = j / HID, k = j % HID;
            float v = (n < NCLS) ? W2[(long)k * NCLS + n] : 0.f;
            g_w2ht[n][k] = __float2half_rn(v);
        }
    }
}

// ---------------- GEMM1 fp16 HMMA: h1h = fp16(x @ W1)  (raw; ns applied in agg1) -----
// BM=128 BN=128 BK=32, 256 thr, warp tile 32x64, m16n8k16.
// 3-stage cp.async pipeline, dynamic smem (84KB).
#define G1_AS_BYTES (3 * 128 * 36 * 4)
#define G1_BS_BYTES (3 * 128 * 40 * 2)
#define G1_SMEM     (G1_AS_BYTES + G1_BS_BYTES)

__global__ __launch_bounds__(256, 2)
void k_gemm1_f16(const float* __restrict__ A, __half* __restrict__ out, int M) {
    extern __shared__ char smem_raw[];
    float  (*As)[128][36] = (float(*)[128][36])smem_raw;
    __half (*Bs)[128][40] = (__half(*)[128][40])(smem_raw + G1_AS_BYTES);

    const int tid  = threadIdx.x;
    const int lane = tid & 31;
    const int w    = tid >> 5;
    const int wm   = w >> 1;
    const int wn   = w & 1;
    const int g    = lane >> 2;
    const int tig  = lane & 3;
    const int rowbase = blockIdx.y * 128;

    float acc[2][8][4];
#pragma unroll
    for (int mi = 0; mi < 2; mi++)
#pragma unroll
        for (int ni = 0; ni < 8; ni++)
#pragma unroll
            for (int j = 0; j < 4; j++) acc[mi][ni][j] = 0.f;

    // A tile: 128 rows x 16 float2 chunks. Warp covers 2 rows, 128B contiguous each.
    auto issueA = [&](int k0, int b) {
#pragma unroll
        for (int i = 0; i < 8; i++) {
            int idx = tid + i * 256;
            int m = idx >> 4, kq2 = idx & 15;
            int k = k0 + kq2 * 2;
            int gm = rowbase + m;
            int valid = (gm < M) && (k < NFEAT);
            const float* src = A + (valid ? ((long)gm * NFEAT + k) : 0);
            cp_async8(&As[b][m][kq2 * 2], src, valid ? 8 : 0);
        }
    };
    // B tile: 128 n-rows x 4 16B chunks, warp covers 8 rows x 64B contiguous.
    auto issueB = [&](int k0, int b) {
#pragma unroll
        for (int i = 0; i < 2; i++) {
            int idx = tid + i * 256;
            int n = idx >> 2, c = idx & 3;
            cp_async16(&Bs[b][n][c * 8], &g_w1ht[n][k0 + c * 8], 16);
        }
    };

    const int NIT = NFEATP / 32;   // 19

    issueA(0, 0);  issueB(0, 0);  cp_commit();
    issueA(32, 1); issueB(32, 1); cp_commit();

    for (int it = 0; it < NIT; it++) {
        const int cur = it % 3;
        cp_wait_1();               // group 'it' complete (newest group may be in flight)
        __syncthreads();
        if (it + 2 < NIT) {
            issueA((it + 2) * 32, (it + 2) % 3);
            issueB((it + 2) * 32, (it + 2) % 3);
        }
        cp_commit();               // one group per iter (possibly empty) keeps tail correct

#pragma unroll
        for (int kk = 0; kk < 32; kk += 16) {
            unsigned afr[2][4];
#pragma unroll
            for (int mi = 0; mi < 2; mi++) {
                int mb = wm * 32 + mi * 16;
                float2 v0 = *(const float2*)&As[cur][mb + g    ][kk + tig * 2];
                float2 v1 = *(const float2*)&As[cur][mb + g + 8][kk + tig * 2];
                float2 v2 = *(const float2*)&As[cur][mb + g    ][kk + tig * 2 + 8];
                float2 v3 = *(const float2*)&As[cur][mb + g + 8][kk + tig * 2 + 8];
                afr[mi][0] = packh2(v0.x, v0.y);
                afr[mi][1] = packh2(v1.x, v1.y);
                afr[mi][2] = packh2(v2.x, v2.y);
                afr[mi][3] = packh2(v3.x, v3.y);
            }
            unsigned bfr[8][2];
#pragma unroll
            for (int ni = 0; ni < 8; ni++) {
                int nb = wn * 64 + ni * 8 + g;
                bfr[ni][0] = *(const unsigned*)&Bs[cur][nb][kk + tig * 2];
                bfr[ni][1] = *(const unsigned*)&Bs[cur][nb][kk + tig * 2 + 8];
            }
#pragma unroll
            for (int mi = 0; mi < 2; mi++)
#pragma unroll
                for (int ni = 0; ni < 8; ni++) {
                    asm volatile(
                        "mma.sync.aligned.m16n8k16.row.col.f32.f16.f16.f32 "
                        "{%0,%1,%2,%3}, {%4,%5,%6,%7}, {%8,%9}, {%0,%1,%2,%3};"
                        : "+f"(acc[mi][ni][0]), "+f"(acc[mi][ni][1]),
                          "+f"(acc[mi][ni][2]), "+f"(acc[mi][ni][3])
                        : "r"(afr[mi][0]), "r"(afr[mi][1]),
                          "r"(afr[mi][2]), "r"(afr[mi][3]),
                          "r"(bfr[ni][0]), "r"(bfr[ni][1]));
                }
        }
        __syncthreads();           // protect buffer (it)%3 until all warps done
    }

#pragma unroll
    for (int mi = 0; mi < 2; mi++) {
        int row0 = rowbase + wm * 32 + mi * 16 + g;
        int row1 = row0 + 8;
#pragma unroll
        for (int ni = 0; ni < 8; ni++) {
            int col = wn * 64 + ni * 8 + tig * 2;
            if (row0 < M)
                *(__half2*)(out + (long)row0 * HID + col) =
                    __floats2half2_rn(acc[mi][ni][0], acc[mi][ni][1]);
            if (row1 < M)
                *(__half2*)(out + (long)row1 * HID + col) =
                    __floats2half2_rn(acc[mi][ni][2], acc[mi][ni][3]);
        }
    }
}

// ---------------- GEMM2 fp16 HMMA: h2h = fp16( ns[row] * (h1bh @ W2) ) ----------------
__global__ __launch_bounds__(256, 2)
void k_gemm2_f16(const float* __restrict__ ns, __half* __restrict__ out, int M) {
    __shared__ __half As[2][128][40];
    __shared__ __half Bs[2][64][40];

    const int tid  = threadIdx.x;
    const int lane = tid & 31;
    const int w    = tid >> 5;
    const int wm   = w >> 1;
    const int wn   = w & 1;
    const int g    = lane >> 2;
    const int tig  = lane & 3;
    const int rowbase = blockIdx.y * 128;

    float acc[2][4][4];
#pragma unroll
    for (int mi = 0; mi < 2; mi++)
#pragma unroll
        for (int ni = 0; ni < 4; ni++)
#pragma unroll
            for (int j = 0; j < 4; j++) acc[mi][ni][j] = 0.f;

    auto issueA = [&](int k0, int b) {
#pragma unroll
        for (int i = 0; i < 2; i++) {
            int idx = tid + i * 256;
            int m = idx >> 2, c = idx & 3;
            int gm = rowbase + m;
            int valid = (gm < M);
            const __half* src = g_h1bh + (valid ? ((size_t)gm * HID + k0 + c * 8) : 0);
            cp_async16(&As[b][m][c * 8], src, valid ? 16 : 0);
        }
    };
    auto issueB = [&](int k0, int b) {
        int n = tid >> 2, c = tid & 3;
        cp_async16(&Bs[b][n][c * 8], &g_w2ht[n][k0 + c * 8], 16);
    };

    const int NIT = HID / 32;   // 4

    issueA(0, 0); issueB(0, 0); cp_commit();

    for (int it = 0; it < NIT; it++) {
        const int cur = it & 1;
        cp_wait_all();
        __syncthreads();
        if (it + 1 < NIT) {
            issueA((it + 1) * 32, cur ^ 1);
            issueB((it + 1) * 32, cur ^ 1);
            cp_commit();
        }

#pragma unroll
        for (int kk = 0; kk < 32; kk += 16) {
            unsigned afr[2][4];
#pragma unroll
            for (int mi = 0; mi < 2; mi++) {
                int mb = wm * 32 + mi * 16;
                afr[mi][0] = *(const unsigned*)&As[cur][mb + g    ][kk + tig * 2];
                afr[mi][1] = *(const unsigned*)&As[cur][mb + g + 8][kk + tig * 2];
                afr[mi][2] = *(const unsigned*)&As[cur][mb + g    ][kk + tig * 2 + 8];
                afr[mi][3] = *(const unsigned*)&As[cur][mb + g + 8][kk + tig * 2 + 8];
            }
            unsigned bfr[4][2];
#pragma unroll
            for (int ni = 0; ni < 4; ni++) {
                int nb = wn * 32 + ni * 8 + g;
                bfr[ni][0] = *(const unsigned*)&Bs[cur][nb][kk + tig * 2];
                bfr[ni][1] = *(const unsigned*)&Bs[cur][nb][kk + tig * 2 + 8];
            }
#pragma unroll
            for (int mi = 0; mi < 2; mi++)
#pragma unroll
                for (int ni = 0; ni < 4; ni++) {
                    asm volatile(
                        "mma.sync.aligned.m16n8k16.row.col.f32.f16.f16.f32 "
                        "{%0,%1,%2,%3}, {%4,%5,%6,%7}, {%8,%9}, {%0,%1,%2,%3};"
                        : "+f"(acc[mi][ni][0]), "+f"(acc[mi][ni][1]),
                          "+f"(acc[mi][ni][2]), "+f"(acc[mi][ni][3])
                        : "r"(afr[mi][0]), "r"(afr[mi][1]),
                          "r"(afr[mi][2]), "r"(afr[mi][3]),
                          "r"(bfr[ni][0]), "r"(bfr[ni][1]));
                }
        }
    }

#pragma unroll
    for (int mi = 0; mi < 2; mi++) {
        int row0 = rowbase + wm * 32 + mi * 16 + g;
        int row1 = row0 + 8;
        float s0 = (row0 < M) ? ns[row0] : 0.f;
        float s1 = (row1 < M) ? ns[row1] : 0.f;
#pragma unroll
        for (int ni = 0; ni < 4; ni++) {
            int col = wn * 32 + ni * 8 + tig * 2;
            if (col <= 40) {
                if (row0 < M)
                    *(__half2*)(out + (long)row0 * H2S + col) =
                        __floats2half2_rn(acc[mi][ni][0] * s0, acc[mi][ni][1] * s0);
                if (row1 < M)
                    *(__half2*)(out + (long)row1 * H2S + col) =
                        __floats2half2_rn(acc[mi][ni][2] * s1, acc[mi][ni][3] * s1);
            }
        }
    }
}

// ---------------- layer-1 aggregation: warp/node fp16 gather, ns[src] fused, fp16 out --
__global__ void k_agg1(const float* __restrict__ b1) {
    int node = (blockIdx.x * blockDim.x + threadIdx.x) >> 5;
    int lane = threadIdx.x & 31;
    if (node >= N_NODES) return;
    int end = g_incl[node];
    int j = end - g_deg_in[node];
    float a0 = 0.f, a1 = 0.f, a2 = 0.f, a3 = 0.f;

    auto body = [&](int s) {
        float nsv = g_ns[s];
        uint2 u = *((const uint2*)(g_h1h + (size_t)s * HID) + lane);
        float2 f0 = __half22float2(*(const __half2*)&u.x);
        float2 f1 = __half22float2(*(const __half2*)&u.y);
        a0 = fmaf(nsv, f0.x, a0);
        a1 = fmaf(nsv, f0.y, a1);
        a2 = fmaf(nsv, f1.x, a2);
        a3 = fmaf(nsv, f1.y, a3);
    };

    for (; j + 4 <= end; j += 4) {
        int s0 = g_csr[j], s1 = g_csr[j + 1], s2 = g_csr[j + 2], s3 = g_csr[j + 3];
        body(s0); body(s1); body(s2); body(s3);
    }
    for (; j < end; j++) body(g_csr[j]);

    float nd = g_nd[node];
    float4 bb = ((const float4*)b1)[lane];
    uint2 o;
    o.x = packh2(fmaxf(a0 * nd + bb.x, 0.f), fmaxf(a1 * nd + bb.y, 0.f));
    o.y = packh2(fmaxf(a2 * nd + bb.z, 0.f), fmaxf(a3 * nd + bb.w, 0.f));
    *((uint2*)(g_h1bh + (size_t)node * HID) + lane) = o;
}

// ---------------- layer-2 aggregation: warp/node fp16 gather, fuse nd+bias ----------------
__global__ void k_agg2(const float* __restrict__ b2, float* __restrict__ out) {
    int node = (blockIdx.x * blockDim.x + threadIdx.x) >> 5;
    int lane = threadIdx.x & 31;
    if (node >= N_NODES) return;
    int end = g_incl[node];
    int j = end - g_deg_in[node];
    int c = lane * 2;
    bool act = (c < NCLS + 1);
    float a0 = 0.f, a1 = 0.f;

    for (; j + 4 <= end; j += 4) {
        int s0 = g_csr[j], s1 = g_csr[j + 1], s2 = g_csr[j + 2], s3 = g_csr[j + 3];
        if (act) {
            float2 f0 = __half22float2(*(const __half2*)(g_h2h + (size_t)s0 * H2S + c));
            float2 f1 = __half22float2(*(const __half2*)(g_h2h + (size_t)s1 * H2S + c));
            float2 f2 = __half22float2(*(const __half2*)(g_h2h + (size_t)s2 * H2S + c));
            float2 f3 = __half22float2(*(const __half2*)(g_h2h + (size_t)s3 * H2S + c));
            a0 += f0.x + f1.x + f2.x + f3.x;
            a1 += f0.y + f1.y + f2.y + f3.y;
        }
    }
    for (; j < end; j++) {
        int s = g_csr[j];
        if (act) {
            float2 f = __half22float2(*(const __half2*)(g_h2h + (size_t)s * H2S + c));
            a0 += f.x; a1 += f.y;
        }
    }
    if (act) {
        float nd = g_nd[node];
        float* po = out + (long)node * NCLS;
        po[c] = a0 * nd + b2[c];
        if (c + 1 < NCLS) po[c + 1] = a1 * nd + b2[c + 1];
    }
}

// ---------------- launcher ----------------
extern "C" void kernel_launch(void* const* d_in, const int* in_sizes, int n_in,
                              void* d_out, int out_size) {
    const float* x    = (const float*)d_in[0];
    const int*   esrc = (const int*)  d_in[1];
    const int*   edst = (const int*)  d_in[2];
    const float* W1   = (const float*)d_in[3];
    const float* b1   = (const float*)d_in[4];
    const float* W2   = (const float*)d_in[5];
    const float* b2   = (const float*)d_in[6];
    float*       out  = (float*)d_out;

    __half *p_h1h, *p_h2h;
    float  *p_ns;
    cudaGetSymbolAddress((void**)&p_h1h, g_h1h);
    cudaGetSymbolAddress((void**)&p_h2h, g_h2h);
    cudaGetSymbolAddress((void**)&p_ns,  g_ns);

    static bool attr_done = false;
    if (!attr_done) {
        cudaFuncSetAttribute(k_gemm1_f16,
                             cudaFuncAttributeMaxDynamicSharedMemorySize, G1_SMEM);
        attr_done = true;
    }

    const int TB = 256;

    // fork: weight-convert + GEMM1 (independent of edges) on s2; CSR chain on stream 0
    cudaEventRecord(g_ev_fork, 0);
    cudaStreamWaitEvent(g_s2, g_ev_fork, 0);
    {
        int tot = 128 * NFEATP + 64 * HID;
        k_cvtW<<<(tot + TB - 1) / TB, TB, 0, g_s2>>>(W1, W2);
        dim3 grid(1, (N_NODES + 127) / 128);
        k_gemm1_f16<<<grid, 256, G1_SMEM, g_s2>>>(x, p_h1h, N_NODES);
    }
    cudaEventRecord(g_ev_join, g_s2);

    // CSR + norms on default stream
    k_zero_deg<<<(N_NODES + TB - 1) / TB, TB>>>();
    k_count   <<<(N_EDGES + TB - 1) / TB, TB>>>(esrc, edst);
    int nb = (N_NODES + 1023) / 1024;
    k_scan_block<<<nb, 1024>>>();
    k_scan_tot  <<<1, 256>>>(nb);
    k_scan_fin  <<<(N_NODES + TB - 1) / TB, TB>>>();
    k_fill      <<<(N_EDGES + TB - 1) / TB, TB>>>(esrc, edst);

    // join: agg1 needs h1h + csr + ns + nd
    cudaStreamWaitEvent(0, g_ev_join, 0);
    k_agg1<<<(N_NODES * 32 + TB - 1) / TB, TB>>>(b1);

    // layer 2 (all fp16 tensor path)
    {
        dim3 grid(1, (N_NODES + 127) / 128);
        k_gemm2_f16<<<grid, 256>>>(p_ns, p_h2h, N_NODES);
    }
    k_agg2<<<(N_NODES * 32 + TB - 1) / TB, TB>>>(b2, out);
}

// round 10
// speedup vs baseline: 8.3072x; 1.1310x over previous
#include <cuda_runtime.h>
#include <cuda_fp16.h>
#include <cuda_bf16.h>

#define N_NODES  100000
#define N_EDGES  1600000
#define NFEAT    602
#define NFEATP   608     // padded to 19*32
#define HID      128
#define NCLS     41
#define H2S      48      // padded h2 row stride in halves (cols 41..47 pad)

// ---------------- device scratch (no allocations allowed) ----------------
__device__ int   g_deg_in[N_NODES];
__device__ int   g_deg_out[N_NODES];
__device__ float g_ns[N_NODES];          // deg_out^-1/2 (clipped)
__device__ float g_nd[N_NODES];          // deg_in^-1/2  (clipped)
__device__ int   g_incl[N_NODES];        // end offset of node's csr bucket
__device__ int   g_total;                // atomic base allocator for fused scan
__device__ int   g_cursor[N_NODES];
__device__ int   g_csr[N_EDGES];         // src ids grouped by dst
__device__ __align__(16) __half g_h1h [(size_t)N_NODES * HID];  // raw x@W1 (no ns), fp16
__device__ __align__(16) __half g_h1bh[(size_t)N_NODES * HID];  // relu'd layer-1 out, fp16
__device__ __align__(16) __half g_h2h [(size_t)N_NODES * H2S];  // ns*(h1b@W2), fp16
__device__ __align__(16) __half g_w1ht[128][NFEATP];            // W1^T fp16, zero-padded
__device__ __align__(16) __half g_w2ht[64][HID];                // W2^T fp16, zero-padded

// ---------------- streams/events for fork-join (created before harness baseline) ----
static cudaStream_t g_s2;
static cudaEvent_t  g_ev_fork, g_ev_join;
namespace {
struct StreamInit {
    StreamInit() {
        cudaStreamCreateWithFlags(&g_s2, cudaStreamNonBlocking);
        cudaEventCreateWithFlags(&g_ev_fork, cudaEventDisableTiming);
        cudaEventCreateWithFlags(&g_ev_join, cudaEventDisableTiming);
    }
};
StreamInit g_stream_init;
}

// ---------------- cp.async helpers ----------------
__device__ __forceinline__ void cp_async16(void* dst, const void* src, int ssize) {
    asm volatile("cp.async.cg.shared.global [%0], [%1], 16, %2;\n" ::
        "r"((unsigned)__cvta_generic_to_shared(dst)), "l"(src), "r"(ssize));
}
__device__ __forceinline__ void cp_commit() {
    asm volatile("cp.async.commit_group;\n" ::: "memory");
}
__device__ __forceinline__ void cp_wait_all() {
    asm volatile("cp.async.wait_group 0;\n" ::: "memory");
}

__device__ __forceinline__ unsigned packh2(float lo, float hi) {
    __half2 h = __floats2half2_rn(lo, hi);
    return *(unsigned*)&h;
}

// ---------------- degree / norm / CSR build ----------------
__global__ void k_zero_deg() {
    int i = blockIdx.x * blockDim.x + threadIdx.x;
    if (i < N_NODES) { g_deg_in[i] = 0; g_deg_out[i] = 0; }
    if (i == 0) g_total = 0;
}

__global__ void k_count(const int* __restrict__ src, const int* __restrict__ dst) {
    int e = blockIdx.x * blockDim.x + threadIdx.x;
    if (e < N_EDGES) {
        atomicAdd(&g_deg_out[src[e]], 1);
        atomicAdd(&g_deg_in [dst[e]], 1);
    }
}

// fused: block scan + atomic block base + cursor/norm write
__global__ void k_scan_fused() {
    __shared__ int s[1024];
    __shared__ int base_sh;
    int i = blockIdx.x * 1024 + threadIdx.x;
    int di = (i < N_NODES) ? g_deg_in[i] : 0;
    s[threadIdx.x] = di;
    __syncthreads();
    for (int off = 1; off < 1024; off <<= 1) {
        int t = (threadIdx.x >= off) ? s[threadIdx.x - off] : 0;
        __syncthreads();
        s[threadIdx.x] += t;
        __syncthreads();
    }
    if (threadIdx.x == 1023) base_sh = atomicAdd(&g_total, s[1023]);
    __syncthreads();
    if (i < N_NODES) {
        int incl = s[threadIdx.x] + base_sh;
        g_incl[i] = incl;
        g_cursor[i] = incl - di;
        int dout = g_deg_out[i];
        g_ns[i] = rsqrtf((float)(dout > 1 ? dout : 1));
        g_nd[i] = rsqrtf((float)(di   > 1 ? di   : 1));
    }
}

__global__ void k_fill(const int* __restrict__ src, const int* __restrict__ dst) {
    int e = blockIdx.x * blockDim.x + threadIdx.x;
    if (e < N_EDGES) {
        int pos = atomicAdd(&g_cursor[dst[e]], 1);
        g_csr[pos] = src[e];
    }
}

// ---------------- weight convert ----------------
__global__ void k_cvtW(const float* __restrict__ W1, const float* __restrict__ W2) {
    int i = blockIdx.x * blockDim.x + threadIdx.x;
    int tot1 = 128 * NFEATP;
    if (i < tot1) {
        int n = i / NFEATP, k = i % NFEATP;
        float v = (k < NFEAT) ? W1[(long)k * HID + n] : 0.f;
        g_w1ht[n][k] = __float2half_rn(v);
    } else {
        int j = i - tot1;
        if (j < 64 * HID) {
            int n = j / HID, k = j % HID;
            float v = (n < NCLS) ? W2[(long)k * NCLS + n] : 0.f;
            g_w2ht[n][k] = __float2half_rn(v);
        }
    }
}

// ---------------- GEMM1 fp16 HMMA: h1h = fp16(x @ W1)  (raw; ns applied in agg1) -----
// BM=128 BN=128 BK=32, 256 thr, warp tile 32x64, m16n8k16.
// A: register-staged LDG.64 pairs (row stride 2408B is only 8B-aligned!) -> fp16 smem.
// B: cp.async double buffer from fp16 W1^T.
#define G1_AS_BYTES (2 * 128 * 40 * 2)
#define G1_BS_BYTES (2 * 128 * 40 * 2)
#define G1_SMEM     (G1_AS_BYTES + G1_BS_BYTES)

__global__ __launch_bounds__(256, 2)
void k_gemm1_f16(const float* __restrict__ A, __half* __restrict__ out, int M) {
    extern __shared__ char smem_raw[];
    __half (*As)[128][40] = (__half(*)[128][40])smem_raw;
    __half (*Bs)[128][40] = (__half(*)[128][40])(smem_raw + G1_AS_BYTES);

    const int tid  = threadIdx.x;
    const int lane = tid & 31;
    const int w    = tid >> 5;
    const int wm   = w >> 1;
    const int wn   = w & 1;
    const int g    = lane >> 2;
    const int tig  = lane & 3;
    const int rowbase = blockIdx.y * 128;

    float acc[2][8][4];
#pragma unroll
    for (int mi = 0; mi < 2; mi++)
#pragma unroll
        for (int ni = 0; ni < 8; ni++)
#pragma unroll
            for (int j = 0; j < 4; j++) acc[mi][ni][j] = 0.f;

    // A reg staging: 128 rows x 8 4-float chunks = 1024; 4 per thread.
    // Global loads are 2x float2 (8B) — A rows are only 8B aligned (2408B stride).
    float4 aReg[4];
    const int am = tid >> 3;       // base row (stride 32 across i)
    const int ac = tid & 7;        // 4-float chunk within 32-k slice

    auto loadA = [&](int k0) {
#pragma unroll
        for (int i = 0; i < 4; i++) {
            int m = am + i * 32;
            int gm = rowbase + m;
            int k = k0 + ac * 4;
            float4 v = make_float4(0.f, 0.f, 0.f, 0.f);
            if (gm < M) {
                const float* p = A + (long)gm * NFEAT + k;
                if (k + 3 < NFEAT) {
                    float2 lo = *(const float2*)p;
                    float2 hi = *(const float2*)(p + 2);
                    v.x = lo.x; v.y = lo.y; v.z = hi.x; v.w = hi.y;
                } else if (k + 1 < NFEAT) {   // k == 600: elems 600,601 valid
                    float2 lo = *(const float2*)p;
                    v.x = lo.x; v.y = lo.y;
                }
                // k >= NFEAT: all zero
            }
            aReg[i] = v;
        }
    };
    auto stsA = [&](int b) {
#pragma unroll
        for (int i = 0; i < 4; i++) {
            int m = am + i * 32;
            uint2 u;
            u.x = packh2(aReg[i].x, aReg[i].y);
            u.y = packh2(aReg[i].z, aReg[i].w);
            *(uint2*)&As[b][m][ac * 4] = u;
        }
    };
    auto issueB = [&](int k0, int b) {
#pragma unroll
        for (int i = 0; i < 2; i++) {
            int idx = tid + i * 256;
            int n = idx >> 2, c = idx & 3;
            cp_async16(&Bs[b][n][c * 8], &g_w1ht[n][k0 + c * 8], 16);
        }
    };

    const int NIT = NFEATP / 32;   // 19

    loadA(0);
    issueB(0, 0); cp_commit();
    stsA(0);
    loadA(32);                      // aReg holds iter-1 data entering the loop

    for (int it = 0; it < NIT; it++) {
        const int cur = it & 1;
        cp_wait_all();              // B(cur) complete
        __syncthreads();            // publish stsA(cur), retire reads of cur^1
        if (it + 1 < NIT) {
            stsA(cur ^ 1);                      // store iter it+1 A (from aReg)
            issueB((it + 1) * 32, cur ^ 1);     // fetch iter it+1 B
            cp_commit();
        }
        if (it + 2 < NIT) loadA((it + 2) * 32); // refill aReg for iter it+2

#pragma unroll
        for (int kk = 0; kk < 32; kk += 16) {
            unsigned afr[2][4];
#pragma unroll
            for (int mi = 0; mi < 2; mi++) {
                int mb = wm * 32 + mi * 16;
                afr[mi][0] = *(const unsigned*)&As[cur][mb + g    ][kk + tig * 2];
                afr[mi][1] = *(const unsigned*)&As[cur][mb + g + 8][kk + tig * 2];
                afr[mi][2] = *(const unsigned*)&As[cur][mb + g    ][kk + tig * 2 + 8];
                afr[mi][3] = *(const unsigned*)&As[cur][mb + g + 8][kk + tig * 2 + 8];
            }
            unsigned bfr[8][2];
#pragma unroll
            for (int ni = 0; ni < 8; ni++) {
                int nb = wn * 64 + ni * 8 + g;
                bfr[ni][0] = *(const unsigned*)&Bs[cur][nb][kk + tig * 2];
                bfr[ni][1] = *(const unsigned*)&Bs[cur][nb][kk + tig * 2 + 8];
            }
#pragma unroll
            for (int mi = 0; mi < 2; mi++)
#pragma unroll
                for (int ni = 0; ni < 8; ni++) {
                    asm volatile(
                        "mma.sync.aligned.m16n8k16.row.col.f32.f16.f16.f32 "
                        "{%0,%1,%2,%3}, {%4,%5,%6,%7}, {%8,%9}, {%0,%1,%2,%3};"
                        : "+f"(acc[mi][ni][0]), "+f"(acc[mi][ni][1]),
                          "+f"(acc[mi][ni][2]), "+f"(acc[mi][ni][3])
                        : "r"(afr[mi][0]), "r"(afr[mi][1]),
                          "r"(afr[mi][2]), "r"(afr[mi][3]),
                          "r"(bfr[ni][0]), "r"(bfr[ni][1]));
                }
        }
    }

#pragma unroll
    for (int mi = 0; mi < 2; mi++) {
        int row0 = rowbase + wm * 32 + mi * 16 + g;
        int row1 = row0 + 8;
#pragma unroll
        for (int ni = 0; ni < 8; ni++) {
            int col = wn * 64 + ni * 8 + tig * 2;
            if (row0 < M)
                *(__half2*)(out + (long)row0 * HID + col) =
                    __floats2half2_rn(acc[mi][ni][0], acc[mi][ni][1]);
            if (row1 < M)
                *(__half2*)(out + (long)row1 * HID + col) =
                    __floats2half2_rn(acc[mi][ni][2], acc[mi][ni][3]);
        }
    }
}

// ---------------- GEMM2 fp16 HMMA: h2h = fp16( ns[row] * (h1bh @ W2) ) ----------------
__global__ __launch_bounds__(256, 2)
void k_gemm2_f16(const float* __restrict__ ns, __half* __restrict__ out, int M) {
    __shared__ __half As[2][128][40];
    __shared__ __half Bs[2][64][40];

    const int tid  = threadIdx.x;
    const int lane = tid & 31;
    const int w    = tid >> 5;
    const int wm   = w >> 1;
    const int wn   = w & 1;
    const int g    = lane >> 2;
    const int tig  = lane & 3;
    const int rowbase = blockIdx.y * 128;

    float acc[2][4][4];
#pragma unroll
    for (int mi = 0; mi < 2; mi++)
#pragma unroll
        for (int ni = 0; ni < 4; ni++)
#pragma unroll
            for (int j = 0; j < 4; j++) acc[mi][ni][j] = 0.f;

    auto issueA = [&](int k0, int b) {
#pragma unroll
        for (int i = 0; i < 2; i++) {
            int idx = tid + i * 256;
            int m = idx >> 2, c = idx & 3;
            int gm = rowbase + m;
            int valid = (gm < M);
            const __half* src = g_h1bh + (valid ? ((size_t)gm * HID + k0 + c * 8) : 0);
            cp_async16(&As[b][m][c * 8], src, valid ? 16 : 0);
        }
    };
    auto issueB = [&](int k0, int b) {
        int n = tid >> 2, c = tid & 3;
        cp_async16(&Bs[b][n][c * 8], &g_w2ht[n][k0 + c * 8], 16);
    };

    const int NIT = HID / 32;   // 4

    issueA(0, 0); issueB(0, 0); cp_commit();

    for (int it = 0; it < NIT; it++) {
        const int cur = it & 1;
        cp_wait_all();
        __syncthreads();
        if (it + 1 < NIT) {
            issueA((it + 1) * 32, cur ^ 1);
            issueB((it + 1) * 32, cur ^ 1);
            cp_commit();
        }

#pragma unroll
        for (int kk = 0; kk < 32; kk += 16) {
            unsigned afr[2][4];
#pragma unroll
            for (int mi = 0; mi < 2; mi++) {
                int mb = wm * 32 + mi * 16;
                afr[mi][0] = *(const unsigned*)&As[cur][mb + g    ][kk + tig * 2];
                afr[mi][1] = *(const unsigned*)&As[cur][mb + g + 8][kk + tig * 2];
                afr[mi][2] = *(const unsigned*)&As[cur][mb + g    ][kk + tig * 2 + 8];
                afr[mi][3] = *(const unsigned*)&As[cur][mb + g + 8][kk + tig * 2 + 8];
            }
            unsigned bfr[4][2];
#pragma unroll
            for (int ni = 0; ni < 4; ni++) {
                int nb = wn * 32 + ni * 8 + g;
                bfr[ni][0] = *(const unsigned*)&Bs[cur][nb][kk + tig * 2];
                bfr[ni][1] = *(const unsigned*)&Bs[cur][nb][kk + tig * 2 + 8];
            }
#pragma unroll
            for (int mi = 0; mi < 2; mi++)
#pragma unroll
                for (int ni = 0; ni < 4; ni++) {
                    asm volatile(
                        "mma.sync.aligned.m16n8k16.row.col.f32.f16.f16.f32 "
                        "{%0,%1,%2,%3}, {%4,%5,%6,%7}, {%8,%9}, {%0,%1,%2,%3};"
                        : "+f"(acc[mi][ni][0]), "+f"(acc[mi][ni][1]),
                          "+f"(acc[mi][ni][2]), "+f"(acc[mi][ni][3])
                        : "r"(afr[mi][0]), "r"(afr[mi][1]),
                          "r"(afr[mi][2]), "r"(afr[mi][3]),
                          "r"(bfr[ni][0]), "r"(bfr[ni][1]));
                }
        }
    }

#pragma unroll
    for (int mi = 0; mi < 2; mi++) {
        int row0 = rowbase + wm * 32 + mi * 16 + g;
        int row1 = row0 + 8;
        float s0 = (row0 < M) ? ns[row0] : 0.f;
        float s1 = (row1 < M) ? ns[row1] : 0.f;
#pragma unroll
        for (int ni = 0; ni < 4; ni++) {
            int col = wn * 32 + ni * 8 + tig * 2;
            if (col <= 40) {
                if (row0 < M)
                    *(__half2*)(out + (long)row0 * H2S + col) =
                        __floats2half2_rn(acc[mi][ni][0] * s0, acc[mi][ni][1] * s0);
                if (row1 < M)
                    *(__half2*)(out + (long)row1 * H2S + col) =
                        __floats2half2_rn(acc[mi][ni][2] * s1, acc[mi][ni][3] * s1);
            }
        }
    }
}

// ---------------- layer-1 aggregation: warp/node fp16 gather, ns[src] fused, fp16 out --
__global__ void k_agg1(const float* __restrict__ b1) {
    int node = (blockIdx.x * blockDim.x + threadIdx.x) >> 5;
    int lane = threadIdx.x & 31;
    if (node >= N_NODES) return;
    int end = g_incl[node];
    int j = end - g_deg_in[node];
    float a0 = 0.f, a1 = 0.f, a2 = 0.f, a3 = 0.f;

    auto body = [&](int s) {
        float nsv = g_ns[s];
        uint2 u = *((const uint2*)(g_h1h + (size_t)s * HID) + lane);
        float2 f0 = __half22float2(*(const __half2*)&u.x);
        float2 f1 = __half22float2(*(const __half2*)&u.y);
        a0 = fmaf(nsv, f0.x, a0);
        a1 = fmaf(nsv, f0.y, a1);
        a2 = fmaf(nsv, f1.x, a2);
        a3 = fmaf(nsv, f1.y, a3);
    };

    for (; j + 4 <= end; j += 4) {
        int s0 = g_csr[j], s1 = g_csr[j + 1], s2 = g_csr[j + 2], s3 = g_csr[j + 3];
        body(s0); body(s1); body(s2); body(s3);
    }
    for (; j < end; j++) body(g_csr[j]);

    float nd = g_nd[node];
    float4 bb = ((const float4*)b1)[lane];
    uint2 o;
    o.x = packh2(fmaxf(a0 * nd + bb.x, 0.f), fmaxf(a1 * nd + bb.y, 0.f));
    o.y = packh2(fmaxf(a2 * nd + bb.z, 0.f), fmaxf(a3 * nd + bb.w, 0.f));
    *((uint2*)(g_h1bh + (size_t)node * HID) + lane) = o;
}

// ---------------- layer-2 aggregation: warp/node fp16 gather, fuse nd+bias ----------------
__global__ void k_agg2(const float* __restrict__ b2, float* __restrict__ out) {
    int node = (blockIdx.x * blockDim.x + threadIdx.x) >> 5;
    int lane = threadIdx.x & 31;
    if (node >= N_NODES) return;
    int end = g_incl[node];
    int j = end - g_deg_in[node];
    int c = lane * 2;
    bool act = (c < NCLS + 1);
    float a0 = 0.f, a1 = 0.f;

    for (; j + 4 <= end; j += 4) {
        int s0 = g_csr[j], s1 = g_csr[j + 1], s2 = g_csr[j + 2], s3 = g_csr[j + 3];
        if (act) {
            float2 f0 = __half22float2(*(const __half2*)(g_h2h + (size_t)s0 * H2S + c));
            float2 f1 = __half22float2(*(const __half2*)(g_h2h + (size_t)s1 * H2S + c));
            float2 f2 = __half22float2(*(const __half2*)(g_h2h + (size_t)s2 * H2S + c));
            float2 f3 = __half22float2(*(const __half2*)(g_h2h + (size_t)s3 * H2S + c));
            a0 += f0.x + f1.x + f2.x + f3.x;
            a1 += f0.y + f1.y + f2.y + f3.y;
        }
    }
    for (; j < end; j++) {
        int s = g_csr[j];
        if (act) {
            float2 f = __half22float2(*(const __half2*)(g_h2h + (size_t)s * H2S + c));
            a0 += f.x; a1 += f.y;
        }
    }
    if (act) {
        float nd = g_nd[node];
        float* po = out + (long)node * NCLS;
        po[c] = a0 * nd + b2[c];
        if (c + 1 < NCLS) po[c + 1] = a1 * nd + b2[c + 1];
    }
}

// ---------------- launcher ----------------
extern "C" void kernel_launch(void* const* d_in, const int* in_sizes, int n_in,
                              void* d_out, int out_size) {
    const float* x    = (const float*)d_in[0];
    const int*   esrc = (const int*)  d_in[1];
    const int*   edst = (const int*)  d_in[2];
    const float* W1   = (const float*)d_in[3];
    const float* b1   = (const float*)d_in[4];
    const float* W2   = (const float*)d_in[5];
    const float* b2   = (const float*)d_in[6];
    float*       out  = (float*)d_out;

    __half *p_h1h, *p_h2h;
    float  *p_ns;
    cudaGetSymbolAddress((void**)&p_h1h, g_h1h);
    cudaGetSymbolAddress((void**)&p_h2h, g_h2h);
    cudaGetSymbolAddress((void**)&p_ns,  g_ns);

    static bool attr_done = false;
    if (!attr_done) {
        cudaFuncSetAttribute(k_gemm1_f16,
                             cudaFuncAttributeMaxDynamicSharedMemorySize, G1_SMEM);
        attr_done = true;
    }

    const int TB = 256;

    // fork: weight-convert + GEMM1 (independent of edges) on s2; CSR chain on stream 0
    cudaEventRecord(g_ev_fork, 0);
    cudaStreamWaitEvent(g_s2, g_ev_fork, 0);
    {
        int tot = 128 * NFEATP + 64 * HID;
        k_cvtW<<<(tot + TB - 1) / TB, TB, 0, g_s2>>>(W1, W2);
        dim3 grid(1, (N_NODES + 127) / 128);
        k_gemm1_f16<<<grid, 256, G1_SMEM, g_s2>>>(x, p_h1h, N_NODES);
    }
    cudaEventRecord(g_ev_join, g_s2);

    // CSR + norms on default stream
    k_zero_deg<<<(N_NODES + TB - 1) / TB, TB>>>();
    k_count   <<<(N_EDGES + TB - 1) / TB, TB>>>(esrc, edst);
    int nb = (N_NODES + 1023) / 1024;
    k_scan_fused<<<nb, 1024>>>();
    k_fill      <<<(N_EDGES + TB - 1) / TB, TB>>>(esrc, edst);

    // join: agg1 needs h1h + csr + ns + nd
    cudaStreamWaitEvent(0, g_ev_join, 0);
    k_agg1<<<(N_NODES * 32 + TB - 1) / TB, TB>>>(b1);

    // layer 2 (all fp16 tensor path)
    {
        dim3 grid(1, (N_NODES + 127) / 128);
        k_gemm2_f16<<<grid, 256>>>(p_ns, p_h2h, N_NODES);
    }
    k_agg2<<<(N_NODES * 32 + TB - 1) / TB, TB>>>(b2, out);
}